// round 5
// baseline (speedup 1.0000x reference)
#include <cuda_runtime.h>
#include <math.h>

// Problem constants
constexpr int CB  = 2;     // batch
constexpr int CT  = 2048;  // seq len
constexpr int CH  = 2048;  // hidden
constexpr int CNH = 16;    // heads
constexpr int CHD = 128;   // head dim

// ---------------------------------------------------------------------------
// Scratch (allocation-free: __device__ globals)
// ---------------------------------------------------------------------------
__device__ float g_q [(size_t)CB * CNH * CT * CHD];  // [B,NH,T,HD]
__device__ float g_k [(size_t)CB * CNH * CT * CHD];
__device__ float g_v [(size_t)CB * CNH * CT * CHD];
__device__ float g_ao[(size_t)CB * CT * CH];         // attention out [B,T,H]

// ---------------------------------------------------------------------------
// GEMM: Y = X @ W^T.  X:[M,K] row-major, W:[N,K] row-major.  M=4096, N=K=2048.
// 128x128 tile, BK=16, 256 threads, 8x8 per thread.
// PERMUTE: write Y into [B,NH,T,HD] layout instead of [M,N] row-major.
// ---------------------------------------------------------------------------
constexpr int GBM = 128, GBN = 128, GBK = 16;

template <bool PERMUTE>
__global__ __launch_bounds__(256, 2) void gemm_nt_kernel(
    const float* __restrict__ X, const float* __restrict__ W,
    float* __restrict__ Y)
{
    constexpr int K = CH;
    constexpr int N = CH;
    __shared__ float Xs[GBK][GBM + 4];
    __shared__ float Ws[GBK][GBN + 4];

    const int tid = threadIdx.x;
    const int ty  = tid >> 4;   // 0..15 -> rows ty*8
    const int tx  = tid & 15;   // 0..15 -> cols tx*4 and 64+tx*4
    const int bm  = blockIdx.y * GBM;
    const int bn  = blockIdx.x * GBN;

    const int lrow = tid >> 2;          // 0..63
    const int lcg4 = (tid & 3) * 4;     // 0,4,8,12

    const float* xp0 = X + (size_t)(bm + lrow) * K + lcg4;
    const float* xp1 = xp0 + (size_t)64 * K;
    const float* wp0 = W + (size_t)(bn + lrow) * K + lcg4;
    const float* wp1 = wp0 + (size_t)64 * K;

    float acc[8][8];
#pragma unroll
    for (int i = 0; i < 8; i++)
#pragma unroll
        for (int j = 0; j < 8; j++) acc[i][j] = 0.f;

    for (int k0 = 0; k0 < K; k0 += GBK) {
        float4 xv0 = *(const float4*)(xp0 + k0);
        float4 xv1 = *(const float4*)(xp1 + k0);
        float4 wv0 = *(const float4*)(wp0 + k0);
        float4 wv1 = *(const float4*)(wp1 + k0);
        __syncthreads();  // previous compute done before smem overwrite
        Xs[lcg4 + 0][lrow]      = xv0.x; Xs[lcg4 + 1][lrow]      = xv0.y;
        Xs[lcg4 + 2][lrow]      = xv0.z; Xs[lcg4 + 3][lrow]      = xv0.w;
        Xs[lcg4 + 0][lrow + 64] = xv1.x; Xs[lcg4 + 1][lrow + 64] = xv1.y;
        Xs[lcg4 + 2][lrow + 64] = xv1.z; Xs[lcg4 + 3][lrow + 64] = xv1.w;
        Ws[lcg4 + 0][lrow]      = wv0.x; Ws[lcg4 + 1][lrow]      = wv0.y;
        Ws[lcg4 + 2][lrow]      = wv0.z; Ws[lcg4 + 3][lrow]      = wv0.w;
        Ws[lcg4 + 0][lrow + 64] = wv1.x; Ws[lcg4 + 1][lrow + 64] = wv1.y;
        Ws[lcg4 + 2][lrow + 64] = wv1.z; Ws[lcg4 + 3][lrow + 64] = wv1.w;
        __syncthreads();

#pragma unroll
        for (int k = 0; k < GBK; k++) {
            float4 a0 = *(const float4*)&Xs[k][ty * 8];
            float4 a1 = *(const float4*)&Xs[k][ty * 8 + 4];
            float4 b0 = *(const float4*)&Ws[k][tx * 4];        // conflict-free
            float4 b1 = *(const float4*)&Ws[k][64 + tx * 4];   // conflict-free
            float av[8] = {a0.x, a0.y, a0.z, a0.w, a1.x, a1.y, a1.z, a1.w};
            float bv[8] = {b0.x, b0.y, b0.z, b0.w, b1.x, b1.y, b1.z, b1.w};
#pragma unroll
            for (int i = 0; i < 8; i++)
#pragma unroll
                for (int j = 0; j < 8; j++)
                    acc[i][j] = fmaf(av[i], bv[j], acc[i][j]);
        }
    }

    // Epilogue. Columns: j<4 -> bn+tx*4+j ; j>=4 -> bn+64+tx*4+(j-4)
    if (PERMUTE) {
#pragma unroll
        for (int i = 0; i < 8; i++) {
            int r  = bm + ty * 8 + i;
            int bi = r >> 11;            // / T
            int t  = r & (CT - 1);
            int c0 = bn + tx * 4;        // head h = c0>>7 (same head for both halves)
            int hh = c0 >> 7;
            int d0 = c0 & 127;
            float* yp = Y + (((size_t)bi * CNH + hh) * CT + t) * CHD;
            *(float4*)(yp + d0)      = make_float4(acc[i][0], acc[i][1], acc[i][2], acc[i][3]);
            *(float4*)(yp + d0 + 64) = make_float4(acc[i][4], acc[i][5], acc[i][6], acc[i][7]);
        }
    } else {
#pragma unroll
        for (int i = 0; i < 8; i++) {
            int r = bm + ty * 8 + i;
            float* yp = Y + (size_t)r * N + bn + tx * 4;
            *(float4*)yp        = make_float4(acc[i][0], acc[i][1], acc[i][2], acc[i][3]);
            *(float4*)(yp + 64) = make_float4(acc[i][4], acc[i][5], acc[i][6], acc[i][7]);
        }
    }
}

// ---------------------------------------------------------------------------
// RoPE in-place on g_q, g_k. One thread per (b,h,t, d<64) pair.
// out[d]    = x[d]*cos[d]    - x[d+64]*sin[d]
// out[d+64] = x[d+64]*cos[d+64] + x[d]*sin[d+64]
// ---------------------------------------------------------------------------
__global__ void rope_kernel(const float* __restrict__ cosb,
                            const float* __restrict__ sinb)
{
    int idx = blockIdx.x * blockDim.x + threadIdx.x;   // < B*NH*T*64 = 2^22
    int d  = idx & 63;
    int t  = (idx >> 6) & (CT - 1);
    int bh = idx >> 17;
    size_t base = ((size_t)bh * CT + t) * CHD;
    float c0 = cosb[t * CHD + d],      c1 = cosb[t * CHD + d + 64];
    float s0 = sinb[t * CHD + d],      s1 = sinb[t * CHD + d + 64];
    float q0 = g_q[base + d], q1 = g_q[base + d + 64];
    g_q[base + d]      = fmaf(q0, c0, -q1 * s0);
    g_q[base + d + 64] = fmaf(q1, c1,  q0 * s1);
    float k0 = g_k[base + d], k1 = g_k[base + d + 64];
    g_k[base + d]      = fmaf(k0, c0, -k1 * s0);
    g_k[base + d + 64] = fmaf(k1, c1,  k0 * s1);
}

// ---------------------------------------------------------------------------
// Flash attention (causal). CTA = (qtile of 64 rows, head, batch). 256 threads.
// Score tile 64x64: thread(ty,tx) owns rows ty*4..+4, kcols tx*4..+4.
// O tile 64x128:    thread(ty,tx) owns rows ty*4..+4, cols {tx*4..+4, 64+tx*4..+4}.
// ---------------------------------------------------------------------------
constexpr int ABQ = 64, ABK = 64;
constexpr int AQS = 68;   // stride for d-major [128][.] tiles (16B-aligned rows)
constexpr int AVS = 132;  // stride for V rows
constexpr int SMEM_ATTN = (128 * AQS * 2 + ABK * AVS + ABK * AQS) * 4;  // ~121 KB

__global__ __launch_bounds__(256) void attn_kernel()
{
    extern __shared__ float sm[];
    float* Qst = sm;                    // [128][AQS]  Q^T, pre-scaled
    float* Kst = Qst + 128 * AQS;       // [128][AQS]  K^T
    float* Vsm = Kst + 128 * AQS;       // [64][AVS]
    float* Pst = Vsm + ABK * AVS;       // [64][AQS]   P^T

    const int qt  = blockIdx.x;
    const int h   = blockIdx.y;
    const int b   = blockIdx.z;
    const int tid = threadIdx.x;
    const int ty  = tid >> 4;
    const int tx  = tid & 15;
    const float scale = 0.08838834764831843f;  // 1/sqrt(128)

    const size_t bh = ((size_t)b * CNH + h) * CT * CHD;
    const float* Qg = g_q + bh;
    const float* Kg = g_k + bh;
    const float* Vg = g_v + bh;

    // Load Q tile transposed (scaled): 2048 float4, 8 per thread
#pragma unroll
    for (int i = 0; i < 8; i++) {
        int f  = tid + i * 256;
        int r  = f >> 5;
        int dg = (f & 31) * 4;
        float4 v = *(const float4*)(Qg + (size_t)(qt * ABQ + r) * CHD + dg);
        Qst[(dg + 0) * AQS + r] = v.x * scale;
        Qst[(dg + 1) * AQS + r] = v.y * scale;
        Qst[(dg + 2) * AQS + r] = v.z * scale;
        Qst[(dg + 3) * AQS + r] = v.w * scale;
    }

    float m_i[4], l_i[4], o[4][8];
#pragma unroll
    for (int i = 0; i < 4; i++) {
        m_i[i] = -3.0e38f; l_i[i] = 0.f;
#pragma unroll
        for (int j = 0; j < 8; j++) o[i][j] = 0.f;
    }

    for (int kt = 0; kt <= qt; kt++) {
        __syncthreads();  // previous iteration's readers done
#pragma unroll
        for (int i = 0; i < 8; i++) {
            int f  = tid + i * 256;
            int r  = f >> 5;
            int dg = (f & 31) * 4;
            float4 kv = *(const float4*)(Kg + (size_t)(kt * ABK + r) * CHD + dg);
            Kst[(dg + 0) * AQS + r] = kv.x;
            Kst[(dg + 1) * AQS + r] = kv.y;
            Kst[(dg + 2) * AQS + r] = kv.z;
            Kst[(dg + 3) * AQS + r] = kv.w;
            float4 vv = *(const float4*)(Vg + (size_t)(kt * ABK + r) * CHD + dg);
            *(float4*)(Vsm + r * AVS + dg) = vv;
        }
        __syncthreads();

        // S = (Q*scale) @ K^T
        float s[4][4];
#pragma unroll
        for (int i = 0; i < 4; i++)
#pragma unroll
            for (int j = 0; j < 4; j++) s[i][j] = 0.f;

#pragma unroll 4
        for (int d = 0; d < 128; d++) {
            float4 a  = *(const float4*)(Qst + d * AQS + ty * 4);
            float4 bb = *(const float4*)(Kst + d * AQS + tx * 4);
            float av[4] = {a.x, a.y, a.z, a.w};
            float bv[4] = {bb.x, bb.y, bb.z, bb.w};
#pragma unroll
            for (int i = 0; i < 4; i++)
#pragma unroll
                for (int j = 0; j < 4; j++)
                    s[i][j] = fmaf(av[i], bv[j], s[i][j]);
        }

        // Causal mask on diagonal tile
        if (kt == qt) {
#pragma unroll
            for (int i = 0; i < 4; i++)
#pragma unroll
                for (int j = 0; j < 4; j++)
                    if (tx * 4 + j > ty * 4 + i) s[i][j] = -3.0e38f;
        }

        // Online softmax. Row group = 16 lanes sharing ty (xor masks 1,2,4,8).
#pragma unroll
        for (int i = 0; i < 4; i++) {
            float rm = fmaxf(fmaxf(s[i][0], s[i][1]), fmaxf(s[i][2], s[i][3]));
#pragma unroll
            for (int off = 8; off >= 1; off >>= 1)
                rm = fmaxf(rm, __shfl_xor_sync(0xffffffffu, rm, off));
            float mn = fmaxf(m_i[i], rm);
            float rs = 0.f;
#pragma unroll
            for (int j = 0; j < 4; j++) {
                s[i][j] = __expf(s[i][j] - mn);
                rs += s[i][j];
            }
#pragma unroll
            for (int off = 8; off >= 1; off >>= 1)
                rs += __shfl_xor_sync(0xffffffffu, rs, off);
            float alpha = __expf(m_i[i] - mn);
            l_i[i] = l_i[i] * alpha + rs;
            m_i[i] = mn;
#pragma unroll
            for (int j = 0; j < 8; j++) o[i][j] *= alpha;
#pragma unroll
            for (int j = 0; j < 4; j++)
                Pst[(tx * 4 + j) * AQS + ty * 4 + i] = s[i][j];
        }
        __syncthreads();

        // O += P @ V
#pragma unroll 2
        for (int kc = 0; kc < ABK; kc++) {
            float4 p  = *(const float4*)(Pst + kc * AQS + ty * 4);
            float4 v0 = *(const float4*)(Vsm + kc * AVS + tx * 4);        // conflict-free
            float4 v1 = *(const float4*)(Vsm + kc * AVS + 64 + tx * 4);   // conflict-free
            float pv[4] = {p.x, p.y, p.z, p.w};
            float vv[8] = {v0.x, v0.y, v0.z, v0.w, v1.x, v1.y, v1.z, v1.w};
#pragma unroll
            for (int i = 0; i < 4; i++)
#pragma unroll
                for (int j = 0; j < 8; j++)
                    o[i][j] = fmaf(pv[i], vv[j], o[i][j]);
        }
    }

    // Epilogue: O /= l ; write [B,T,H] layout
#pragma unroll
    for (int i = 0; i < 4; i++) {
        int qg = qt * ABQ + ty * 4 + i;
        float inv = 1.f / l_i[i];
        float* op = g_ao + ((size_t)b * CT + qg) * CH + h * CHD;
        *(float4*)(op + tx * 4) =
            make_float4(o[i][0] * inv, o[i][1] * inv, o[i][2] * inv, o[i][3] * inv);
        *(float4*)(op + 64 + tx * 4) =
            make_float4(o[i][4] * inv, o[i][5] * inv, o[i][6] * inv, o[i][7] * inv);
    }
}

// ---------------------------------------------------------------------------
// Launch
// ---------------------------------------------------------------------------
extern "C" void kernel_launch(void* const* d_in, const int* in_sizes, int n_in,
                              void* d_out, int out_size)
{
    (void)in_sizes; (void)n_in; (void)out_size;
    const float* x    = (const float*)d_in[0];
    const float* cosb = (const float*)d_in[1];
    const float* sinb = (const float*)d_in[2];
    const float* Wq   = (const float*)d_in[3];
    const float* Wk   = (const float*)d_in[4];
    const float* Wv   = (const float*)d_in[5];
    const float* Wo   = (const float*)d_in[6];
    float* out = (float*)d_out;

    float *qp, *kp, *vp, *aop;
    cudaGetSymbolAddress((void**)&qp,  g_q);
    cudaGetSymbolAddress((void**)&kp,  g_k);
    cudaGetSymbolAddress((void**)&vp,  g_v);
    cudaGetSymbolAddress((void**)&aop, g_ao);

    cudaFuncSetAttribute(attn_kernel,
                         cudaFuncAttributeMaxDynamicSharedMemorySize, SMEM_ATTN);

    dim3 gg(CH / GBN, (CB * CT) / GBM);   // (16, 32)
    gemm_nt_kernel<true><<<gg, 256>>>(x, Wq, qp);
    gemm_nt_kernel<true><<<gg, 256>>>(x, Wk, kp);
    gemm_nt_kernel<true><<<gg, 256>>>(x, Wv, vp);
    rope_kernel<<<(CB * CNH * CT * 64) / 256, 256>>>(cosb, sinb);
    attn_kernel<<<dim3(CT / ABQ, CNH, CB), 256, SMEM_ATTN>>>();
    gemm_nt_kernel<false><<<gg, 256>>>(aop, Wo, out);
}

// round 7
// speedup vs baseline: 1.6209x; 1.6209x over previous
#include <cuda_runtime.h>
#include <cuda_bf16.h>
#include <cstdint>
#include <math.h>

// Problem constants
constexpr int CB  = 2;     // batch
constexpr int CT  = 2048;  // seq len
constexpr int CH  = 2048;  // hidden
constexpr int CNH = 16;    // heads
constexpr int CHD = 128;   // head dim
constexpr int GM  = CB * CT;   // 4096 GEMM rows
constexpr int GK  = CH;        // 2048
constexpr int GN  = CH;        // 2048

// ---------------------------------------------------------------------------
// Scratch (allocation-free: __device__ globals)
// ---------------------------------------------------------------------------
__device__ float g_q [(size_t)CB * CNH * CT * CHD];  // [B,NH,T,HD]
__device__ float g_k [(size_t)CB * CNH * CT * CHD];
__device__ float g_v [(size_t)CB * CNH * CT * CHD];
__device__ float g_ao[(size_t)CB * CT * CH];         // attention out [B,T,H]

// split-bf16 planes
__device__ __align__(16) __nv_bfloat16 g_xh [(size_t)GM * GK];
__device__ __align__(16) __nv_bfloat16 g_xl [(size_t)GM * GK];
__device__ __align__(16) __nv_bfloat16 g_wh [4][(size_t)GN * GK];  // q,k,v,o
__device__ __align__(16) __nv_bfloat16 g_wl [4][(size_t)GN * GK];
__device__ __align__(16) __nv_bfloat16 g_aoh[(size_t)GM * GK];
__device__ __align__(16) __nv_bfloat16 g_aol[(size_t)GM * GK];

// ---------------------------------------------------------------------------
// Baseline-ISA tensor-core helpers (valid on compute_103 virtual arch)
// ---------------------------------------------------------------------------
__device__ __forceinline__ uint32_t smem_to_u32(const void* p) {
    uint32_t a;
    asm("{ .reg .u64 t; cvta.to.shared.u64 t, %1; cvt.u32.u64 %0, t; }"
        : "=r"(a) : "l"(p));
    return a;
}

__device__ __forceinline__ void ldmx4(uint32_t* r, uint32_t addr) {
    asm volatile("ldmatrix.sync.aligned.m8n8.x4.shared.b16 {%0,%1,%2,%3}, [%4];"
        : "=r"(r[0]), "=r"(r[1]), "=r"(r[2]), "=r"(r[3]) : "r"(addr));
}

// D(16x8,f32) += A(16x16,bf16) row-major x B(16x8,bf16) "col" (both K-contig)
__device__ __forceinline__ void mma16816(float* d, const uint32_t* a,
                                         const uint32_t* b) {
    asm volatile(
        "mma.sync.aligned.m16n8k16.row.col.f32.bf16.bf16.f32 "
        "{%0,%1,%2,%3}, {%4,%5,%6,%7}, {%8,%9}, {%0,%1,%2,%3};"
        : "+f"(d[0]), "+f"(d[1]), "+f"(d[2]), "+f"(d[3])
        : "r"(a[0]), "r"(a[1]), "r"(a[2]), "r"(a[3]), "r"(b[0]), "r"(b[1]));
}

// ---------------------------------------------------------------------------
// Split-precision conversion: hi = bf16(x), lo = bf16(x - hi). 4 elems/thread.
// ---------------------------------------------------------------------------
__global__ void cvt_split_kernel(const float* __restrict__ src,
                                 __nv_bfloat16* __restrict__ hi,
                                 __nv_bfloat16* __restrict__ lo, int n4)
{
    int i = blockIdx.x * blockDim.x + threadIdx.x;
    if (i >= n4) return;
    float4 v = ((const float4*)src)[i];
    __nv_bfloat16 h[4], l[4];
    h[0] = __float2bfloat16(v.x); l[0] = __float2bfloat16(v.x - __bfloat162float(h[0]));
    h[1] = __float2bfloat16(v.y); l[1] = __float2bfloat16(v.y - __bfloat162float(h[1]));
    h[2] = __float2bfloat16(v.z); l[2] = __float2bfloat16(v.z - __bfloat162float(h[2]));
    h[3] = __float2bfloat16(v.w); l[3] = __float2bfloat16(v.w - __bfloat162float(h[3]));
    *(uint2*)(hi + (size_t)i * 4) = *(uint2*)h;
    *(uint2*)(lo + (size_t)i * 4) = *(uint2*)l;
}

// ---------------------------------------------------------------------------
// mma.sync bf16 GEMM with split compensation: Y = A @ B^T (fp32 out).
// A:[GM,GK], B:[GN,GK], both row-major K-contiguous, hi/lo planes each.
// CTA 128x128, BK=32, 8 warps (2m x 4n), warp tile 64x32, double-buffered.
// Smem rows padded to 40 bf16 (80 B): stride 80 mod 128 hits all eight 16B
// slots -> conflict-free ldmatrix.
// ---------------------------------------------------------------------------
constexpr int BK = 32;
constexpr int ROWB = 80;                         // padded row bytes (40 bf16)
constexpr int TILE_BYTES  = 128 * ROWB;          // 10240
constexpr int STAGE_BYTES = 4 * TILE_BYTES;      // Ah, Al, Bh, Bl = 40960
constexpr int SMEM_GEMM   = 2 * STAGE_BYTES;     // 81920
constexpr int NKB = GK / BK;                     // 64

template <bool PERMUTE>
__global__ __launch_bounds__(256) void gemm_mma_kernel(
    const __nv_bfloat16* __restrict__ Ah, const __nv_bfloat16* __restrict__ Al,
    const __nv_bfloat16* __restrict__ Bh, const __nv_bfloat16* __restrict__ Bl,
    float* __restrict__ Y)
{
    extern __shared__ char sm[];
    const uint32_t sb = smem_to_u32(sm);
    const int tid = threadIdx.x;
    const int wid = tid >> 5;
    const int lid = tid & 31;
    const int wm  = wid & 1;        // warp m index (0..1)
    const int wn  = wid >> 1;       // warp n index (0..3)
    const int bn  = blockIdx.x * 128;
    const int bm  = blockIdx.y * 128;

    // ldmatrix lane decomposition
    const int lg = lid >> 3;        // group 0..3
    const int li = lid & 7;         // row within group

    float acc[4][4][4];
#pragma unroll
    for (int mt = 0; mt < 4; mt++)
#pragma unroll
        for (int nt = 0; nt < 4; nt++)
#pragma unroll
            for (int r = 0; r < 4; r++) acc[mt][nt][r] = 0.f;

    // loader: thread -> chunk c (16B), rows r0 and r0+64 of each tile
    const int lc = tid & 3;
    const int lr = tid >> 2;        // 0..63

    auto load_stage = [&](int s, int kb) {
        const size_t go = (size_t)kb * BK + lc * 8;
        char* st = sm + s * STAGE_BYTES;
        const int so = lr * ROWB + lc * 16;
        const int so2 = (lr + 64) * ROWB + lc * 16;
        // Ah
        *(uint4*)(st + 0 * TILE_BYTES + so ) = *(const uint4*)(Ah + (size_t)(bm + lr) * GK + go);
        *(uint4*)(st + 0 * TILE_BYTES + so2) = *(const uint4*)(Ah + (size_t)(bm + lr + 64) * GK + go);
        // Al
        *(uint4*)(st + 1 * TILE_BYTES + so ) = *(const uint4*)(Al + (size_t)(bm + lr) * GK + go);
        *(uint4*)(st + 1 * TILE_BYTES + so2) = *(const uint4*)(Al + (size_t)(bm + lr + 64) * GK + go);
        // Bh
        *(uint4*)(st + 2 * TILE_BYTES + so ) = *(const uint4*)(Bh + (size_t)(bn + lr) * GK + go);
        *(uint4*)(st + 2 * TILE_BYTES + so2) = *(const uint4*)(Bh + (size_t)(bn + lr + 64) * GK + go);
        // Bl
        *(uint4*)(st + 3 * TILE_BYTES + so ) = *(const uint4*)(Bl + (size_t)(bn + lr) * GK + go);
        *(uint4*)(st + 3 * TILE_BYTES + so2) = *(const uint4*)(Bl + (size_t)(bn + lr + 64) * GK + go);
    };

    load_stage(0, 0);

    for (int kb = 0; kb < NKB; kb++) {
        const int buf = kb & 1;
        __syncthreads();                 // stage `buf` ready; prev readers done
        if (kb + 1 < NKB) load_stage(buf ^ 1, kb + 1);

        const uint32_t sAh = sb + buf * STAGE_BYTES + 0 * TILE_BYTES;
        const uint32_t sAl = sb + buf * STAGE_BYTES + 1 * TILE_BYTES;
        const uint32_t sBh = sb + buf * STAGE_BYTES + 2 * TILE_BYTES;
        const uint32_t sBl = sb + buf * STAGE_BYTES + 3 * TILE_BYTES;

#pragma unroll
        for (int ks = 0; ks < 2; ks++) {
            const int ko = ks * 32;      // byte offset of this k16 step
            // A address: groups (g&1)->m half, (g>>1)->k half
            const int aoff = ( (lg & 1) * 8 + li ) * ROWB + ko + (lg >> 1) * 16;
            // B address: groups (g>>1)->n half, (g&1)->k half
            const int boff = ( (lg >> 1) * 8 + li ) * ROWB + ko + (lg & 1) * 16;

            uint32_t ah[4][4], al[4][4], bh[4][2], bl[4][2];
#pragma unroll
            for (int mt = 0; mt < 4; mt++) {
                int mrow = (wm * 64 + mt * 16) * ROWB;
                ldmx4(ah[mt], sAh + mrow + aoff);
            }
#pragma unroll
            for (int p = 0; p < 2; p++) {
                int nrow = (wn * 32 + p * 16) * ROWB;
                uint32_t r[4];
                ldmx4(r, sBh + nrow + boff);
                bh[2*p][0] = r[0]; bh[2*p][1] = r[1];
                bh[2*p+1][0] = r[2]; bh[2*p+1][1] = r[3];
            }
            // pass 1: Ah x Bh
#pragma unroll
            for (int mt = 0; mt < 4; mt++)
#pragma unroll
                for (int nt = 0; nt < 4; nt++)
                    mma16816(acc[mt][nt], ah[mt], bh[nt]);

#pragma unroll
            for (int p = 0; p < 2; p++) {
                int nrow = (wn * 32 + p * 16) * ROWB;
                uint32_t r[4];
                ldmx4(r, sBl + nrow + boff);
                bl[2*p][0] = r[0]; bl[2*p][1] = r[1];
                bl[2*p+1][0] = r[2]; bl[2*p+1][1] = r[3];
            }
            // pass 2: Ah x Bl
#pragma unroll
            for (int mt = 0; mt < 4; mt++)
#pragma unroll
                for (int nt = 0; nt < 4; nt++)
                    mma16816(acc[mt][nt], ah[mt], bl[nt]);

#pragma unroll
            for (int mt = 0; mt < 4; mt++) {
                int mrow = (wm * 64 + mt * 16) * ROWB;
                ldmx4(al[mt], sAl + mrow + aoff);
            }
            // pass 3: Al x Bh
#pragma unroll
            for (int mt = 0; mt < 4; mt++)
#pragma unroll
                for (int nt = 0; nt < 4; nt++)
                    mma16816(acc[mt][nt], al[mt], bh[nt]);
        }
    }

    // Epilogue. D frag: lane l -> row l/4 (and +8), cols 2*(l%4), +1
    const int er = lid >> 2;          // 0..7
    const int ec = (lid & 3) * 2;
#pragma unroll
    for (int mt = 0; mt < 4; mt++) {
#pragma unroll
        for (int half = 0; half < 2; half++) {
            int row = bm + wm * 64 + mt * 16 + half * 8 + er;
            float* yp;
            if (PERMUTE) {
                int b = row >> 11;
                int t = row & (CT - 1);
                int head = bn >> 7;   // bn multiple of 128 -> one head per tile
                yp = Y + (((size_t)b * CNH + head) * CT + t) * CHD;
            } else {
                yp = Y + (size_t)row * GN + bn;
            }
#pragma unroll
            for (int nt = 0; nt < 4; nt++) {
                int nc = wn * 32 + nt * 8 + ec;
                *(float2*)(yp + nc) = make_float2(acc[mt][nt][half * 2 + 0],
                                                  acc[mt][nt][half * 2 + 1]);
            }
        }
    }
}

// ---------------------------------------------------------------------------
// RoPE in-place on g_q, g_k (unchanged from passing R5 kernel).
// ---------------------------------------------------------------------------
__global__ void rope_kernel(const float* __restrict__ cosb,
                            const float* __restrict__ sinb)
{
    int idx = blockIdx.x * blockDim.x + threadIdx.x;   // < B*NH*T*64 = 2^22
    int d  = idx & 63;
    int t  = (idx >> 6) & (CT - 1);
    int bh = idx >> 17;
    size_t base = ((size_t)bh * CT + t) * CHD;
    float c0 = cosb[t * CHD + d],      c1 = cosb[t * CHD + d + 64];
    float s0 = sinb[t * CHD + d],      s1 = sinb[t * CHD + d + 64];
    float q0 = g_q[base + d], q1 = g_q[base + d + 64];
    g_q[base + d]      = fmaf(q0, c0, -q1 * s0);
    g_q[base + d + 64] = fmaf(q1, c1,  q0 * s1);
    float k0 = g_k[base + d], k1 = g_k[base + d + 64];
    g_k[base + d]      = fmaf(k0, c0, -k1 * s0);
    g_k[base + d + 64] = fmaf(k1, c1,  k0 * s1);
}

// ---------------------------------------------------------------------------
// Flash attention (causal), fp32 — unchanged from passing R5 kernel.
// ---------------------------------------------------------------------------
constexpr int ABQ = 64, ABK = 64;
constexpr int AQS = 68;
constexpr int AVS = 132;
constexpr int SMEM_ATTN = (128 * AQS * 2 + ABK * AVS + ABK * AQS) * 4;

__global__ __launch_bounds__(256) void attn_kernel()
{
    extern __shared__ float smf[];
    float* Qst = smf;
    float* Kst = Qst + 128 * AQS;
    float* Vsm = Kst + 128 * AQS;
    float* Pst = Vsm + ABK * AVS;

    const int qt  = blockIdx.x;
    const int h   = blockIdx.y;
    const int b   = blockIdx.z;
    const int tid = threadIdx.x;
    const int ty  = tid >> 4;
    const int tx  = tid & 15;
    const float scale = 0.08838834764831843f;

    const size_t bh = ((size_t)b * CNH + h) * CT * CHD;
    const float* Qg = g_q + bh;
    const float* Kg = g_k + bh;
    const float* Vg = g_v + bh;

#pragma unroll
    for (int i = 0; i < 8; i++) {
        int f  = tid + i * 256;
        int r  = f >> 5;
        int dg = (f & 31) * 4;
        float4 v = *(const float4*)(Qg + (size_t)(qt * ABQ + r) * CHD + dg);
        Qst[(dg + 0) * AQS + r] = v.x * scale;
        Qst[(dg + 1) * AQS + r] = v.y * scale;
        Qst[(dg + 2) * AQS + r] = v.z * scale;
        Qst[(dg + 3) * AQS + r] = v.w * scale;
    }

    float m_i[4], l_i[4], o[4][8];
#pragma unroll
    for (int i = 0; i < 4; i++) {
        m_i[i] = -3.0e38f; l_i[i] = 0.f;
#pragma unroll
        for (int j = 0; j < 8; j++) o[i][j] = 0.f;
    }

    for (int kt = 0; kt <= qt; kt++) {
        __syncthreads();
#pragma unroll
        for (int i = 0; i < 8; i++) {
            int f  = tid + i * 256;
            int r  = f >> 5;
            int dg = (f & 31) * 4;
            float4 kv = *(const float4*)(Kg + (size_t)(kt * ABK + r) * CHD + dg);
            Kst[(dg + 0) * AQS + r] = kv.x;
            Kst[(dg + 1) * AQS + r] = kv.y;
            Kst[(dg + 2) * AQS + r] = kv.z;
            Kst[(dg + 3) * AQS + r] = kv.w;
            float4 vv = *(const float4*)(Vg + (size_t)(kt * ABK + r) * CHD + dg);
            *(float4*)(Vsm + r * AVS + dg) = vv;
        }
        __syncthreads();

        float s[4][4];
#pragma unroll
        for (int i = 0; i < 4; i++)
#pragma unroll
            for (int j = 0; j < 4; j++) s[i][j] = 0.f;

#pragma unroll 4
        for (int d = 0; d < 128; d++) {
            float4 a  = *(const float4*)(Qst + d * AQS + ty * 4);
            float4 bb = *(const float4*)(Kst + d * AQS + tx * 4);
            float av[4] = {a.x, a.y, a.z, a.w};
            float bv[4] = {bb.x, bb.y, bb.z, bb.w};
#pragma unroll
            for (int i = 0; i < 4; i++)
#pragma unroll
                for (int j = 0; j < 4; j++)
                    s[i][j] = fmaf(av[i], bv[j], s[i][j]);
        }

        if (kt == qt) {
#pragma unroll
            for (int i = 0; i < 4; i++)
#pragma unroll
                for (int j = 0; j < 4; j++)
                    if (tx * 4 + j > ty * 4 + i) s[i][j] = -3.0e38f;
        }

#pragma unroll
        for (int i = 0; i < 4; i++) {
            float rm = fmaxf(fmaxf(s[i][0], s[i][1]), fmaxf(s[i][2], s[i][3]));
#pragma unroll
            for (int off = 8; off >= 1; off >>= 1)
                rm = fmaxf(rm, __shfl_xor_sync(0xffffffffu, rm, off));
            float mn = fmaxf(m_i[i], rm);
            float rs = 0.f;
#pragma unroll
            for (int j = 0; j < 4; j++) {
                s[i][j] = __expf(s[i][j] - mn);
                rs += s[i][j];
            }
#pragma unroll
            for (int off = 8; off >= 1; off >>= 1)
                rs += __shfl_xor_sync(0xffffffffu, rs, off);
            float alpha = __expf(m_i[i] - mn);
            l_i[i] = l_i[i] * alpha + rs;
            m_i[i] = mn;
#pragma unroll
            for (int j = 0; j < 8; j++) o[i][j] *= alpha;
#pragma unroll
            for (int j = 0; j < 4; j++)
                Pst[(tx * 4 + j) * AQS + ty * 4 + i] = s[i][j];
        }
        __syncthreads();

#pragma unroll 2
        for (int kc = 0; kc < ABK; kc++) {
            float4 p  = *(const float4*)(Pst + kc * AQS + ty * 4);
            float4 v0 = *(const float4*)(Vsm + kc * AVS + tx * 4);
            float4 v1 = *(const float4*)(Vsm + kc * AVS + 64 + tx * 4);
            float pv[4] = {p.x, p.y, p.z, p.w};
            float vv[8] = {v0.x, v0.y, v0.z, v0.w, v1.x, v1.y, v1.z, v1.w};
#pragma unroll
            for (int i = 0; i < 4; i++)
#pragma unroll
                for (int j = 0; j < 8; j++)
                    o[i][j] = fmaf(pv[i], vv[j], o[i][j]);
        }
    }

#pragma unroll
    for (int i = 0; i < 4; i++) {
        int qg = qt * ABQ + ty * 4 + i;
        float inv = 1.f / l_i[i];
        float* op = g_ao + ((size_t)b * CT + qg) * CH + h * CHD;
        *(float4*)(op + tx * 4) =
            make_float4(o[i][0] * inv, o[i][1] * inv, o[i][2] * inv, o[i][3] * inv);
        *(float4*)(op + 64 + tx * 4) =
            make_float4(o[i][4] * inv, o[i][5] * inv, o[i][6] * inv, o[i][7] * inv);
    }
}

// ---------------------------------------------------------------------------
// Launch
// ---------------------------------------------------------------------------
extern "C" void kernel_launch(void* const* d_in, const int* in_sizes, int n_in,
                              void* d_out, int out_size)
{
    (void)in_sizes; (void)n_in; (void)out_size;
    const float* x    = (const float*)d_in[0];
    const float* cosb = (const float*)d_in[1];
    const float* sinb = (const float*)d_in[2];
    const float* Wq   = (const float*)d_in[3];
    const float* Wk   = (const float*)d_in[4];
    const float* Wv   = (const float*)d_in[5];
    const float* Wo   = (const float*)d_in[6];
    float* out = (float*)d_out;

    float *qp, *kp, *vp, *aop;
    cudaGetSymbolAddress((void**)&qp,  g_q);
    cudaGetSymbolAddress((void**)&kp,  g_k);
    cudaGetSymbolAddress((void**)&vp,  g_v);
    cudaGetSymbolAddress((void**)&aop, g_ao);
    __nv_bfloat16 *xh, *xl, *wh, *wl, *aoh, *aol;
    cudaGetSymbolAddress((void**)&xh,  g_xh);
    cudaGetSymbolAddress((void**)&xl,  g_xl);
    cudaGetSymbolAddress((void**)&wh,  g_wh);
    cudaGetSymbolAddress((void**)&wl,  g_wl);
    cudaGetSymbolAddress((void**)&aoh, g_aoh);
    cudaGetSymbolAddress((void**)&aol, g_aol);

    cudaFuncSetAttribute(attn_kernel,
                         cudaFuncAttributeMaxDynamicSharedMemorySize, SMEM_ATTN);
    cudaFuncSetAttribute(gemm_mma_kernel<true>,
                         cudaFuncAttributeMaxDynamicSharedMemorySize, SMEM_GEMM);
    cudaFuncSetAttribute(gemm_mma_kernel<false>,
                         cudaFuncAttributeMaxDynamicSharedMemorySize, SMEM_GEMM);

    const size_t WSZ = (size_t)GN * GK;          // one weight plane
    const int n4x = GM * GK / 4;
    const int n4w = GN * GK / 4;

    // split conversions
    cvt_split_kernel<<<(n4x + 255) / 256, 256>>>(x,  xh, xl, n4x);
    cvt_split_kernel<<<(n4w + 255) / 256, 256>>>(Wq, wh + 0 * WSZ, wl + 0 * WSZ, n4w);
    cvt_split_kernel<<<(n4w + 255) / 256, 256>>>(Wk, wh + 1 * WSZ, wl + 1 * WSZ, n4w);
    cvt_split_kernel<<<(n4w + 255) / 256, 256>>>(Wv, wh + 2 * WSZ, wl + 2 * WSZ, n4w);
    cvt_split_kernel<<<(n4w + 255) / 256, 256>>>(Wo, wh + 3 * WSZ, wl + 3 * WSZ, n4w);

    // tensor-core projection GEMMs (write directly into [B,NH,T,HD])
    dim3 gg(GN / 128, GM / 128);  // (16, 32)
    gemm_mma_kernel<true><<<gg, 256, SMEM_GEMM>>>(xh, xl, wh + 0 * WSZ, wl + 0 * WSZ, qp);
    gemm_mma_kernel<true><<<gg, 256, SMEM_GEMM>>>(xh, xl, wh + 1 * WSZ, wl + 1 * WSZ, kp);
    gemm_mma_kernel<true><<<gg, 256, SMEM_GEMM>>>(xh, xl, wh + 2 * WSZ, wl + 2 * WSZ, vp);

    rope_kernel<<<(CB * CNH * CT * 64) / 256, 256>>>(cosb, sinb);
    attn_kernel<<<dim3(CT / ABQ, CNH, CB), 256, SMEM_ATTN>>>();

    // output projection
    cvt_split_kernel<<<(n4x + 255) / 256, 256>>>(aop, aoh, aol, n4x);
    gemm_mma_kernel<false><<<gg, 256, SMEM_GEMM>>>(aoh, aol, wh + 3 * WSZ, wl + 3 * WSZ, out);
}

// round 8
// speedup vs baseline: 2.4228x; 1.4948x over previous
#include <cuda_runtime.h>
#include <cuda_bf16.h>
#include <cstdint>
#include <math.h>

// Problem constants
constexpr int CB  = 2;     // batch
constexpr int CT  = 2048;  // seq len
constexpr int CH  = 2048;  // hidden
constexpr int CNH = 16;    // heads
constexpr int CHD = 128;   // head dim
constexpr int GM  = CB * CT;   // 4096
constexpr int GK  = CH;        // 2048
constexpr int GN  = CH;        // 2048

// ---------------------------------------------------------------------------
// Scratch (allocation-free: __device__ globals)
// ---------------------------------------------------------------------------
__device__ float g_q [(size_t)CB * CNH * CT * CHD];  // fp32 Q pre-RoPE [B,NH,T,HD]
__device__ float g_k [(size_t)CB * CNH * CT * CHD];

// split-bf16 planes
__device__ __align__(16) __nv_bfloat16 g_xh [(size_t)GM * GK];
__device__ __align__(16) __nv_bfloat16 g_xl [(size_t)GM * GK];
__device__ __align__(16) __nv_bfloat16 g_wh [4][(size_t)GN * GK];  // q,k,v,o
__device__ __align__(16) __nv_bfloat16 g_wl [4][(size_t)GN * GK];
__device__ __align__(16) __nv_bfloat16 g_qh [(size_t)CB * CNH * CT * CHD];  // scaled
__device__ __align__(16) __nv_bfloat16 g_ql [(size_t)CB * CNH * CT * CHD];
__device__ __align__(16) __nv_bfloat16 g_kh [(size_t)CB * CNH * CT * CHD];
__device__ __align__(16) __nv_bfloat16 g_kl [(size_t)CB * CNH * CT * CHD];
__device__ __align__(16) __nv_bfloat16 g_vh [(size_t)CB * CNH * CT * CHD];
__device__ __align__(16) __nv_bfloat16 g_vl [(size_t)CB * CNH * CT * CHD];
__device__ __align__(16) __nv_bfloat16 g_aoh[(size_t)GM * GK];  // attn out [B*T][H]
__device__ __align__(16) __nv_bfloat16 g_aol[(size_t)GM * GK];

// ---------------------------------------------------------------------------
// Baseline-ISA helpers (all valid on compute_103 virtual arch)
// ---------------------------------------------------------------------------
__device__ __forceinline__ uint32_t smem_to_u32(const void* p) {
    uint32_t a;
    asm("{ .reg .u64 t; cvta.to.shared.u64 t, %1; cvt.u32.u64 %0, t; }"
        : "=r"(a) : "l"(p));
    return a;
}
__device__ __forceinline__ void ldmx4(uint32_t* r, uint32_t addr) {
    asm volatile("ldmatrix.sync.aligned.m8n8.x4.shared.b16 {%0,%1,%2,%3}, [%4];"
        : "=r"(r[0]), "=r"(r[1]), "=r"(r[2]), "=r"(r[3]) : "r"(addr));
}
__device__ __forceinline__ void ldmx4t(uint32_t* r, uint32_t addr) {
    asm volatile("ldmatrix.sync.aligned.m8n8.x4.trans.shared.b16 {%0,%1,%2,%3}, [%4];"
        : "=r"(r[0]), "=r"(r[1]), "=r"(r[2]), "=r"(r[3]) : "r"(addr));
}
__device__ __forceinline__ void mma16816(float* d, const uint32_t* a,
                                         const uint32_t* b) {
    asm volatile(
        "mma.sync.aligned.m16n8k16.row.col.f32.bf16.bf16.f32 "
        "{%0,%1,%2,%3}, {%4,%5,%6,%7}, {%8,%9}, {%0,%1,%2,%3};"
        : "+f"(d[0]), "+f"(d[1]), "+f"(d[2]), "+f"(d[3])
        : "r"(a[0]), "r"(a[1]), "r"(a[2]), "r"(a[3]), "r"(b[0]), "r"(b[1]));
}
__device__ __forceinline__ void cp_async16(uint32_t dst, const void* src) {
    asm volatile("cp.async.cg.shared.global [%0], [%1], 16;"
        :: "r"(dst), "l"(src));
}
#define CP_COMMIT() asm volatile("cp.async.commit_group;" ::: "memory")
#define CP_WAIT0()  asm volatile("cp.async.wait_group 0;" ::: "memory")
#define CP_WAIT1()  asm volatile("cp.async.wait_group 1;" ::: "memory")

__device__ __forceinline__ uint32_t pack_bf16(float a, float b) {
    __nv_bfloat162 h = __float22bfloat162_rn(make_float2(a, b));
    return *(uint32_t*)&h;
}

// ---------------------------------------------------------------------------
// Split conversion: hi = bf16(x), lo = bf16(x - hi)
// ---------------------------------------------------------------------------
__global__ void cvt_split_kernel(const float* __restrict__ src,
                                 __nv_bfloat16* __restrict__ hi,
                                 __nv_bfloat16* __restrict__ lo, int n4)
{
    int i = blockIdx.x * blockDim.x + threadIdx.x;
    if (i >= n4) return;
    float4 v = ((const float4*)src)[i];
    __nv_bfloat16 h[4], l[4];
    h[0] = __float2bfloat16(v.x); l[0] = __float2bfloat16(v.x - __bfloat162float(h[0]));
    h[1] = __float2bfloat16(v.y); l[1] = __float2bfloat16(v.y - __bfloat162float(h[1]));
    h[2] = __float2bfloat16(v.z); l[2] = __float2bfloat16(v.z - __bfloat162float(h[2]));
    h[3] = __float2bfloat16(v.w); l[3] = __float2bfloat16(v.w - __bfloat162float(h[3]));
    *(uint2*)(hi + (size_t)i * 4) = *(uint2*)h;
    *(uint2*)(lo + (size_t)i * 4) = *(uint2*)l;
}

// ---------------------------------------------------------------------------
// GEMM Y = A @ B^T, split-bf16 3-pass, cp.async 3-stage pipeline.
// MODE 0: fp32 row-major [GM][GN]; MODE 1: fp32 permuted [B,NH,T,HD];
// MODE 2: split-bf16 permuted (for V).
// ---------------------------------------------------------------------------
constexpr int BKG = 32;
constexpr int ROWB = 80;                         // 64B data + 16 pad
constexpr int TILE_BYTES  = 128 * ROWB;          // 10240
constexpr int STAGE_BYTES = 4 * TILE_BYTES;      // Ah, Al, Bh, Bl
constexpr int SMEM_GEMM   = 3 * STAGE_BYTES;     // 122880
constexpr int NKB = GK / BKG;                    // 64

template <int MODE>
__global__ __launch_bounds__(256) void gemm_mma_kernel(
    const __nv_bfloat16* __restrict__ Ah, const __nv_bfloat16* __restrict__ Al,
    const __nv_bfloat16* __restrict__ Bh, const __nv_bfloat16* __restrict__ Bl,
    float* __restrict__ Y, __nv_bfloat16* __restrict__ Yh,
    __nv_bfloat16* __restrict__ Yl)
{
    extern __shared__ char sm[];
    const uint32_t sb = smem_to_u32(sm);
    const int tid = threadIdx.x;
    const int wid = tid >> 5, lid = tid & 31;
    const int wm = wid & 1, wn = wid >> 1;
    const int bn = blockIdx.x * 128, bm = blockIdx.y * 128;
    const int lg = lid >> 3, li = lid & 7;

    float acc[4][4][4];
#pragma unroll
    for (int mt = 0; mt < 4; mt++)
#pragma unroll
        for (int nt = 0; nt < 4; nt++)
#pragma unroll
            for (int r = 0; r < 4; r++) acc[mt][nt][r] = 0.f;

    auto issue_stage = [&](int s, int kb) {
#pragma unroll
        for (int i = 0; i < 8; i++) {
            int f = tid + i * 256;
            int pl = f >> 9, rem = f & 511, row = rem >> 2, c = rem & 3;
            const __nv_bfloat16* sp = (pl == 0) ? Ah : (pl == 1) ? Al
                                     : (pl == 2) ? Bh : Bl;
            int rbase = (pl >= 2) ? bn : bm;
            cp_async16(sb + s * STAGE_BYTES + pl * TILE_BYTES + row * ROWB + c * 16,
                       sp + (size_t)(rbase + row) * GK + kb * BKG + c * 8);
        }
    };

    issue_stage(0, 0); CP_COMMIT();
    issue_stage(1, 1); CP_COMMIT();

    for (int kb = 0; kb < NKB; kb++) {
        if (kb + 1 < NKB) { CP_WAIT1(); } else { CP_WAIT0(); }
        __syncthreads();
        if (kb + 2 < NKB) { issue_stage((kb + 2) % 3, kb + 2); CP_COMMIT(); }

        const uint32_t st = sb + (kb % 3) * STAGE_BYTES;
        const uint32_t sAh = st, sAl = st + TILE_BYTES;
        const uint32_t sBh = st + 2 * TILE_BYTES, sBl = st + 3 * TILE_BYTES;

#pragma unroll
        for (int ks = 0; ks < 2; ks++) {
            const int ko = ks * 32;
            const int aoff = ((lg & 1) * 8 + li) * ROWB + ko + (lg >> 1) * 16;
            const int boff = ((lg >> 1) * 8 + li) * ROWB + ko + (lg & 1) * 16;

            uint32_t ah[4][4], al[4][4], bh[4][2], bl[4][2];
#pragma unroll
            for (int mt = 0; mt < 4; mt++)
                ldmx4(ah[mt], sAh + (wm * 64 + mt * 16) * ROWB + aoff);
#pragma unroll
            for (int p = 0; p < 2; p++) {
                uint32_t r[4];
                ldmx4(r, sBh + (wn * 32 + p * 16) * ROWB + boff);
                bh[2*p][0] = r[0]; bh[2*p][1] = r[1];
                bh[2*p+1][0] = r[2]; bh[2*p+1][1] = r[3];
            }
#pragma unroll
            for (int mt = 0; mt < 4; mt++)
#pragma unroll
                for (int nt = 0; nt < 4; nt++)
                    mma16816(acc[mt][nt], ah[mt], bh[nt]);
#pragma unroll
            for (int p = 0; p < 2; p++) {
                uint32_t r[4];
                ldmx4(r, sBl + (wn * 32 + p * 16) * ROWB + boff);
                bl[2*p][0] = r[0]; bl[2*p][1] = r[1];
                bl[2*p+1][0] = r[2]; bl[2*p+1][1] = r[3];
            }
#pragma unroll
            for (int mt = 0; mt < 4; mt++)
#pragma unroll
                for (int nt = 0; nt < 4; nt++)
                    mma16816(acc[mt][nt], ah[mt], bl[nt]);
#pragma unroll
            for (int mt = 0; mt < 4; mt++)
                ldmx4(al[mt], sAl + (wm * 64 + mt * 16) * ROWB + aoff);
#pragma unroll
            for (int mt = 0; mt < 4; mt++)
#pragma unroll
                for (int nt = 0; nt < 4; nt++)
                    mma16816(acc[mt][nt], al[mt], bh[nt]);
        }
    }

    const int er = lid >> 2;
    const int ec = (lid & 3) * 2;
#pragma unroll
    for (int mt = 0; mt < 4; mt++) {
#pragma unroll
        for (int half = 0; half < 2; half++) {
            int row = bm + wm * 64 + mt * 16 + half * 8 + er;
            size_t base;
            if (MODE == 0) {
                base = (size_t)row * GN + bn;
            } else {
                int b = row >> 11;
                int t = row & (CT - 1);
                int head = bn >> 7;
                base = (((size_t)b * CNH + head) * CT + t) * CHD;
            }
#pragma unroll
            for (int nt = 0; nt < 4; nt++) {
                int nc = wn * 32 + nt * 8 + ec;
                float v0 = acc[mt][nt][half * 2 + 0];
                float v1 = acc[mt][nt][half * 2 + 1];
                if (MODE == 2) {
                    __nv_bfloat162 h2 = __float22bfloat162_rn(make_float2(v0, v1));
                    *(uint32_t*)(Yh + base + nc) = *(uint32_t*)&h2;
                    float l0 = v0 - __bfloat162float(h2.x);
                    float l1 = v1 - __bfloat162float(h2.y);
                    *(uint32_t*)(Yl + base + nc) = pack_bf16(l0, l1);
                } else {
                    *(float2*)(Y + base + nc) = make_float2(v0, v1);
                }
            }
        }
    }
}

// ---------------------------------------------------------------------------
// RoPE + split: reads fp32 g_q/g_k, writes split bf16 (Q pre-scaled).
// ---------------------------------------------------------------------------
__global__ void rope_split_kernel(const float* __restrict__ cosb,
                                  const float* __restrict__ sinb)
{
    const float scale = 0.08838834764831843f;  // 1/sqrt(128)
    int idx = blockIdx.x * blockDim.x + threadIdx.x;   // < B*NH*T*64
    int d  = idx & 63;
    int t  = (idx >> 6) & (CT - 1);
    int bh = idx >> 17;
    size_t base = ((size_t)bh * CT + t) * CHD;
    float c0 = cosb[t * CHD + d],      c1 = cosb[t * CHD + d + 64];
    float s0 = sinb[t * CHD + d],      s1 = sinb[t * CHD + d + 64];
    float q0 = g_q[base + d], q1 = g_q[base + d + 64];
    float qa = fmaf(q0, c0, -q1 * s0) * scale;
    float qb = fmaf(q1, c1,  q0 * s1) * scale;
    float k0 = g_k[base + d], k1 = g_k[base + d + 64];
    float ka = fmaf(k0, c0, -k1 * s0);
    float kb = fmaf(k1, c1,  k0 * s1);
    __nv_bfloat16 h;
    h = __float2bfloat16(qa); g_qh[base + d] = h;
    g_ql[base + d] = __float2bfloat16(qa - __bfloat162float(h));
    h = __float2bfloat16(qb); g_qh[base + d + 64] = h;
    g_ql[base + d + 64] = __float2bfloat16(qb - __bfloat162float(h));
    h = __float2bfloat16(ka); g_kh[base + d] = h;
    g_kl[base + d] = __float2bfloat16(ka - __bfloat162float(h));
    h = __float2bfloat16(kb); g_kh[base + d + 64] = h;
    g_kl[base + d + 64] = __float2bfloat16(kb - __bfloat162float(h));
}

// ---------------------------------------------------------------------------
// Tensor-core flash attention (causal), split-bf16 3-pass for S and PV.
// CTA = (q-tile 128 rows, head, batch); 8 warps, warp w owns rows 16w..+15.
// K-tiles of 64, cp.async double-buffered. Output written split-bf16.
// ---------------------------------------------------------------------------
constexpr int KROWB    = 272;                    // 256B data + 16 pad
constexpr int KV_PLANE = 64 * KROWB;             // 17408
constexpr int KV_STAGE = 4 * KV_PLANE;           // kh,kl,vh,vl
constexpr int SMEM_ATTN = 2 * KV_STAGE;          // 139264

__global__ __launch_bounds__(256) void attn_mma_kernel()
{
    extern __shared__ char sm[];
    const uint32_t sb = smem_to_u32(sm);
    const int qt = blockIdx.x, h = blockIdx.y, b = blockIdx.z;
    const int tid = threadIdx.x, w = tid >> 5, l = tid & 31;
    const size_t bh = ((size_t)b * CNH + h) * CT * CHD;
    const int fr = l >> 2, t2 = (l & 3) * 2;     // frag row / col-pair base
    const int lg = l >> 3, li = l & 7;

    // --- Q hi fragments cached in registers (scaled upstream) ---
    const __nv_bfloat16* qhp = g_qh + bh + (size_t)(qt * 128 + w * 16) * CHD;
    const __nv_bfloat16* qlp = g_ql + bh + (size_t)(qt * 128 + w * 16) * CHD;
    uint32_t qhf[8][4];
#pragma unroll
    for (int ks = 0; ks < 8; ks++) {
        int c = ks * 16 + t2;
        qhf[ks][0] = *(const uint32_t*)(qhp + fr * 128 + c);
        qhf[ks][1] = *(const uint32_t*)(qhp + (fr + 8) * 128 + c);
        qhf[ks][2] = *(const uint32_t*)(qhp + fr * 128 + c + 8);
        qhf[ks][3] = *(const uint32_t*)(qhp + (fr + 8) * 128 + c + 8);
    }

    float o[16][4];
#pragma unroll
    for (int nt = 0; nt < 16; nt++)
#pragma unroll
        for (int e = 0; e < 4; e++) o[nt][e] = 0.f;
    float mx[2] = {-1e30f, -1e30f}, ls[2] = {0.f, 0.f};

    const int last = 2 * qt + 1;

    auto issue = [&](int s, int kt) {
        const __nv_bfloat16* srcs[4] = {
            g_kh + bh + (size_t)kt * 64 * CHD, g_kl + bh + (size_t)kt * 64 * CHD,
            g_vh + bh + (size_t)kt * 64 * CHD, g_vl + bh + (size_t)kt * 64 * CHD};
#pragma unroll
        for (int i = 0; i < 16; i++) {
            int f = tid + i * 256;
            int pl = f >> 10, rem = f & 1023, row = rem >> 4, c = rem & 15;
            cp_async16(sb + s * KV_STAGE + pl * KV_PLANE + row * KROWB + c * 16,
                       srcs[pl] + row * 128 + c * 8);
        }
    };

    issue(0, 0); CP_COMMIT();

    for (int kt = 0; kt <= last; kt++) {
        if (kt < last) { issue((kt + 1) & 1, kt + 1); CP_COMMIT(); CP_WAIT1(); }
        else           { CP_WAIT0(); }
        __syncthreads();

        const uint32_t st = sb + (kt & 1) * KV_STAGE;
        const uint32_t kh_s = st, kl_s = st + KV_PLANE;
        const uint32_t vh_s = st + 2 * KV_PLANE, vl_s = st + 3 * KV_PLANE;

        // ---- S = Qs @ K^T (3 passes) ----
        float s4[8][4];
#pragma unroll
        for (int nt = 0; nt < 8; nt++)
#pragma unroll
            for (int e = 0; e < 4; e++) s4[nt][e] = 0.f;

        const int boffb = ((lg >> 1) * 8 + li) * KROWB + (lg & 1) * 16;
#pragma unroll
        for (int ks = 0; ks < 8; ks++) {
            uint32_t bf[8][2];
#pragma unroll
            for (int p = 0; p < 4; p++) {
                uint32_t r[4];
                ldmx4(r, kh_s + p * 16 * KROWB + ks * 32 + boffb);
                bf[2*p][0] = r[0]; bf[2*p][1] = r[1];
                bf[2*p+1][0] = r[2]; bf[2*p+1][1] = r[3];
            }
#pragma unroll
            for (int nt = 0; nt < 8; nt++) mma16816(s4[nt], qhf[ks], bf[nt]);
            // Ql pass (fragments loaded from global, L1-resident)
            uint32_t qlf[4];
            int c = ks * 16 + t2;
            qlf[0] = *(const uint32_t*)(qlp + fr * 128 + c);
            qlf[1] = *(const uint32_t*)(qlp + (fr + 8) * 128 + c);
            qlf[2] = *(const uint32_t*)(qlp + fr * 128 + c + 8);
            qlf[3] = *(const uint32_t*)(qlp + (fr + 8) * 128 + c + 8);
#pragma unroll
            for (int nt = 0; nt < 8; nt++) mma16816(s4[nt], qlf, bf[nt]);
        }
#pragma unroll
        for (int ks = 0; ks < 8; ks++) {
            uint32_t bf[8][2];
#pragma unroll
            for (int p = 0; p < 4; p++) {
                uint32_t r[4];
                ldmx4(r, kl_s + p * 16 * KROWB + ks * 32 + boffb);
                bf[2*p][0] = r[0]; bf[2*p][1] = r[1];
                bf[2*p+1][0] = r[2]; bf[2*p+1][1] = r[3];
            }
#pragma unroll
            for (int nt = 0; nt < 8; nt++) mma16816(s4[nt], qhf[ks], bf[nt]);
        }

        // ---- causal mask (only the last two tiles can cross the diagonal) ----
        if (kt >= 2 * qt) {
            int row0 = qt * 128 + w * 16 + fr;
#pragma unroll
            for (int nt = 0; nt < 8; nt++) {
                int col0 = kt * 64 + nt * 8 + t2;
#pragma unroll
                for (int e = 0; e < 4; e++) {
                    int row = row0 + 8 * (e >> 1);
                    int col = col0 + (e & 1);
                    if (col > row) s4[nt][e] = -1e30f;
                }
            }
        }

        // ---- online softmax (rows fr, fr+8) ----
#pragma unroll
        for (int half = 0; half < 2; half++) {
            float rm = -1e30f;
#pragma unroll
            for (int nt = 0; nt < 8; nt++)
                rm = fmaxf(rm, fmaxf(s4[nt][2*half], s4[nt][2*half+1]));
            rm = fmaxf(rm, __shfl_xor_sync(0xffffffffu, rm, 1));
            rm = fmaxf(rm, __shfl_xor_sync(0xffffffffu, rm, 2));
            float mn = fmaxf(mx[half], rm);
            float al = __expf(mx[half] - mn);
            mx[half] = mn;
            float rs = 0.f;
#pragma unroll
            for (int nt = 0; nt < 8; nt++) {
                s4[nt][2*half]   = __expf(s4[nt][2*half]   - mn);
                s4[nt][2*half+1] = __expf(s4[nt][2*half+1] - mn);
                rs += s4[nt][2*half] + s4[nt][2*half+1];
            }
            rs += __shfl_xor_sync(0xffffffffu, rs, 1);
            rs += __shfl_xor_sync(0xffffffffu, rs, 2);
            ls[half] = ls[half] * al + rs;
#pragma unroll
            for (int nt = 0; nt < 16; nt++) {
                o[nt][2*half]   *= al;
                o[nt][2*half+1] *= al;
            }
        }

        // ---- P fragments (hi/lo) directly from S fragments ----
        uint32_t pha[4][4], pla[4][4];
#pragma unroll
        for (int kc = 0; kc < 4; kc++) {
#pragma unroll
            for (int j = 0; j < 4; j++) {
                int nt = 2 * kc + (j >> 1);
                int eb = (j & 1) * 2;
                float x0 = s4[nt][eb], x1 = s4[nt][eb + 1];
                __nv_bfloat162 h2 = __float22bfloat162_rn(make_float2(x0, x1));
                pha[kc][j] = *(uint32_t*)&h2;
                pla[kc][j] = pack_bf16(x0 - __bfloat162float(h2.x),
                                       x1 - __bfloat162float(h2.y));
            }
        }

        // ---- O += P @ V (3 passes) ----
#pragma unroll
        for (int kc = 0; kc < 4; kc++) {
            uint32_t vb[16][2];
#pragma unroll
            for (int p = 0; p < 8; p++) {
                uint32_t r[4];
                uint32_t addr = vh_s + (kc * 16 + (lg & 1) * 8 + li) * KROWB
                                + (p * 16 + (lg >> 1) * 8) * 2;
                ldmx4t(r, addr);
                vb[2*p][0] = r[0]; vb[2*p][1] = r[1];
                vb[2*p+1][0] = r[2]; vb[2*p+1][1] = r[3];
            }
#pragma unroll
            for (int nt = 0; nt < 16; nt++) mma16816(o[nt], pha[kc], vb[nt]);
#pragma unroll
            for (int nt = 0; nt < 16; nt++) mma16816(o[nt], pla[kc], vb[nt]);
#pragma unroll
            for (int p = 0; p < 8; p++) {
                uint32_t r[4];
                uint32_t addr = vl_s + (kc * 16 + (lg & 1) * 8 + li) * KROWB
                                + (p * 16 + (lg >> 1) * 8) * 2;
                ldmx4t(r, addr);
                vb[2*p][0] = r[0]; vb[2*p][1] = r[1];
                vb[2*p+1][0] = r[2]; vb[2*p+1][1] = r[3];
            }
#pragma unroll
            for (int nt = 0; nt < 16; nt++) mma16816(o[nt], pha[kc], vb[nt]);
        }
        __syncthreads();   // all warps done with this stage before reuse
    }

    // ---- epilogue: O /= l; write split-bf16 [B*T][H] ----
    float inv0 = 1.f / ls[0], inv1 = 1.f / ls[1];
    int row0 = qt * 128 + w * 16 + fr;
    size_t r0 = ((size_t)b * CT + row0) * CH + h * CHD;
    size_t r1 = ((size_t)b * CT + row0 + 8) * CH + h * CHD;
#pragma unroll
    for (int nt = 0; nt < 16; nt++) {
        int col = nt * 8 + t2;
        float v0 = o[nt][0] * inv0, v1 = o[nt][1] * inv0;
        __nv_bfloat162 h2 = __float22bfloat162_rn(make_float2(v0, v1));
        *(uint32_t*)(g_aoh + r0 + col) = *(uint32_t*)&h2;
        *(uint32_t*)(g_aol + r0 + col) =
            pack_bf16(v0 - __bfloat162float(h2.x), v1 - __bfloat162float(h2.y));
        float v2 = o[nt][2] * inv1, v3 = o[nt][3] * inv1;
        __nv_bfloat162 h3 = __float22bfloat162_rn(make_float2(v2, v3));
        *(uint32_t*)(g_aoh + r1 + col) = *(uint32_t*)&h3;
        *(uint32_t*)(g_aol + r1 + col) =
            pack_bf16(v2 - __bfloat162float(h3.x), v3 - __bfloat162float(h3.y));
    }
}

// ---------------------------------------------------------------------------
// Launch
// ---------------------------------------------------------------------------
extern "C" void kernel_launch(void* const* d_in, const int* in_sizes, int n_in,
                              void* d_out, int out_size)
{
    (void)in_sizes; (void)n_in; (void)out_size;
    const float* x    = (const float*)d_in[0];
    const float* cosb = (const float*)d_in[1];
    const float* sinb = (const float*)d_in[2];
    const float* Wq   = (const float*)d_in[3];
    const float* Wk   = (const float*)d_in[4];
    const float* Wv   = (const float*)d_in[5];
    const float* Wo   = (const float*)d_in[6];
    float* out = (float*)d_out;

    float *qp, *kp;
    cudaGetSymbolAddress((void**)&qp, g_q);
    cudaGetSymbolAddress((void**)&kp, g_k);
    __nv_bfloat16 *xh, *xl, *wh, *wl, *vh, *vl, *aoh, *aol;
    cudaGetSymbolAddress((void**)&xh,  g_xh);
    cudaGetSymbolAddress((void**)&xl,  g_xl);
    cudaGetSymbolAddress((void**)&wh,  g_wh);
    cudaGetSymbolAddress((void**)&wl,  g_wl);
    cudaGetSymbolAddress((void**)&vh,  g_vh);
    cudaGetSymbolAddress((void**)&vl,  g_vl);
    cudaGetSymbolAddress((void**)&aoh, g_aoh);
    cudaGetSymbolAddress((void**)&aol, g_aol);

    cudaFuncSetAttribute(attn_mma_kernel,
                         cudaFuncAttributeMaxDynamicSharedMemorySize, SMEM_ATTN);
    cudaFuncSetAttribute(gemm_mma_kernel<0>,
                         cudaFuncAttributeMaxDynamicSharedMemorySize, SMEM_GEMM);
    cudaFuncSetAttribute(gemm_mma_kernel<1>,
                         cudaFuncAttributeMaxDynamicSharedMemorySize, SMEM_GEMM);
    cudaFuncSetAttribute(gemm_mma_kernel<2>,
                         cudaFuncAttributeMaxDynamicSharedMemorySize, SMEM_GEMM);

    const size_t WSZ = (size_t)GN * GK;
    const int n4x = GM * GK / 4;
    const int n4w = GN * GK / 4;

    cvt_split_kernel<<<(n4x + 255) / 256, 256>>>(x,  xh, xl, n4x);
    cvt_split_kernel<<<(n4w + 255) / 256, 256>>>(Wq, wh + 0 * WSZ, wl + 0 * WSZ, n4w);
    cvt_split_kernel<<<(n4w + 255) / 256, 256>>>(Wk, wh + 1 * WSZ, wl + 1 * WSZ, n4w);
    cvt_split_kernel<<<(n4w + 255) / 256, 256>>>(Wv, wh + 2 * WSZ, wl + 2 * WSZ, n4w);
    cvt_split_kernel<<<(n4w + 255) / 256, 256>>>(Wo, wh + 3 * WSZ, wl + 3 * WSZ, n4w);

    dim3 gg(GN / 128, GM / 128);  // (16, 32)
    gemm_mma_kernel<1><<<gg, 256, SMEM_GEMM>>>(xh, xl, wh + 0 * WSZ, wl + 0 * WSZ,
                                               qp, nullptr, nullptr);
    gemm_mma_kernel<1><<<gg, 256, SMEM_GEMM>>>(xh, xl, wh + 1 * WSZ, wl + 1 * WSZ,
                                               kp, nullptr, nullptr);
    gemm_mma_kernel<2><<<gg, 256, SMEM_GEMM>>>(xh, xl, wh + 2 * WSZ, wl + 2 * WSZ,
                                               nullptr, vh, vl);

    rope_split_kernel<<<(CB * CNH * CT * 64) / 256, 256>>>(cosb, sinb);
    attn_mma_kernel<<<dim3(CT / 128, CNH, CB), 256, SMEM_ATTN>>>();

    gemm_mma_kernel<0><<<gg, 256, SMEM_GEMM>>>(aoh, aol, wh + 3 * WSZ, wl + 3 * WSZ,
                                               out, nullptr, nullptr);
}

// round 9
// speedup vs baseline: 2.6584x; 1.0973x over previous
#include <cuda_runtime.h>
#include <cuda_bf16.h>
#include <cstdint>
#include <math.h>

// Problem constants
constexpr int CB  = 2;     // batch
constexpr int CT  = 2048;  // seq len
constexpr int CH  = 2048;  // hidden
constexpr int CNH = 16;    // heads
constexpr int CHD = 128;   // head dim
constexpr int GM  = CB * CT;   // 4096
constexpr int GK  = CH;        // 2048
constexpr int GN  = CH;        // 2048

// ---------------------------------------------------------------------------
// Scratch (allocation-free: __device__ globals)
// ---------------------------------------------------------------------------
__device__ float g_q [(size_t)CB * CNH * CT * CHD];  // fp32 Q pre-RoPE [B,NH,T,HD]
__device__ float g_k [(size_t)CB * CNH * CT * CHD];

// split-bf16 planes
__device__ __align__(16) __nv_bfloat16 g_xh [(size_t)GM * GK];
__device__ __align__(16) __nv_bfloat16 g_xl [(size_t)GM * GK];
__device__ __align__(16) __nv_bfloat16 g_wh [4][(size_t)GN * GK];  // q,k,v,o
__device__ __align__(16) __nv_bfloat16 g_wl [4][(size_t)GN * GK];
__device__ __align__(16) __nv_bfloat16 g_qh [(size_t)CB * CNH * CT * CHD];  // scaled
__device__ __align__(16) __nv_bfloat16 g_ql [(size_t)CB * CNH * CT * CHD];
__device__ __align__(16) __nv_bfloat16 g_kh [(size_t)CB * CNH * CT * CHD];
__device__ __align__(16) __nv_bfloat16 g_kl [(size_t)CB * CNH * CT * CHD];
__device__ __align__(16) __nv_bfloat16 g_vh [(size_t)CB * CNH * CT * CHD];
__device__ __align__(16) __nv_bfloat16 g_vl [(size_t)CB * CNH * CT * CHD];
__device__ __align__(16) __nv_bfloat16 g_aoh[(size_t)GM * GK];  // attn out [B*T][H]
__device__ __align__(16) __nv_bfloat16 g_aol[(size_t)GM * GK];

// ---------------------------------------------------------------------------
// Baseline-ISA helpers (all valid on compute_103 virtual arch)
// ---------------------------------------------------------------------------
__device__ __forceinline__ uint32_t smem_to_u32(const void* p) {
    uint32_t a;
    asm("{ .reg .u64 t; cvta.to.shared.u64 t, %1; cvt.u32.u64 %0, t; }"
        : "=r"(a) : "l"(p));
    return a;
}
__device__ __forceinline__ void ldmx4(uint32_t* r, uint32_t addr) {
    asm volatile("ldmatrix.sync.aligned.m8n8.x4.shared.b16 {%0,%1,%2,%3}, [%4];"
        : "=r"(r[0]), "=r"(r[1]), "=r"(r[2]), "=r"(r[3]) : "r"(addr));
}
__device__ __forceinline__ void ldmx4t(uint32_t* r, uint32_t addr) {
    asm volatile("ldmatrix.sync.aligned.m8n8.x4.trans.shared.b16 {%0,%1,%2,%3}, [%4];"
        : "=r"(r[0]), "=r"(r[1]), "=r"(r[2]), "=r"(r[3]) : "r"(addr));
}
__device__ __forceinline__ void mma16816(float* d, const uint32_t* a,
                                         const uint32_t* b) {
    asm volatile(
        "mma.sync.aligned.m16n8k16.row.col.f32.bf16.bf16.f32 "
        "{%0,%1,%2,%3}, {%4,%5,%6,%7}, {%8,%9}, {%0,%1,%2,%3};"
        : "+f"(d[0]), "+f"(d[1]), "+f"(d[2]), "+f"(d[3])
        : "r"(a[0]), "r"(a[1]), "r"(a[2]), "r"(a[3]), "r"(b[0]), "r"(b[1]));
}
__device__ __forceinline__ void cp_async16(uint32_t dst, const void* src) {
    asm volatile("cp.async.cg.shared.global [%0], [%1], 16;"
        :: "r"(dst), "l"(src));
}
#define CP_COMMIT() asm volatile("cp.async.commit_group;" ::: "memory")
#define CP_WAIT0()  asm volatile("cp.async.wait_group 0;" ::: "memory")
#define CP_WAIT1()  asm volatile("cp.async.wait_group 1;" ::: "memory")

__device__ __forceinline__ uint32_t pack_bf16(float a, float b) {
    __nv_bfloat162 h = __float22bfloat162_rn(make_float2(a, b));
    return *(uint32_t*)&h;
}

// ---------------------------------------------------------------------------
// Split conversion: hi = bf16(x), lo = bf16(x - hi)
// ---------------------------------------------------------------------------
__global__ void cvt_split_kernel(const float* __restrict__ src,
                                 __nv_bfloat16* __restrict__ hi,
                                 __nv_bfloat16* __restrict__ lo, int n4)
{
    int i = blockIdx.x * blockDim.x + threadIdx.x;
    if (i >= n4) return;
    float4 v = ((const float4*)src)[i];
    __nv_bfloat16 h[4], l[4];
    h[0] = __float2bfloat16(v.x); l[0] = __float2bfloat16(v.x - __bfloat162float(h[0]));
    h[1] = __float2bfloat16(v.y); l[1] = __float2bfloat16(v.y - __bfloat162float(h[1]));
    h[2] = __float2bfloat16(v.z); l[2] = __float2bfloat16(v.z - __bfloat162float(h[2]));
    h[3] = __float2bfloat16(v.w); l[3] = __float2bfloat16(v.w - __bfloat162float(h[3]));
    *(uint2*)(hi + (size_t)i * 4) = *(uint2*)h;
    *(uint2*)(lo + (size_t)i * 4) = *(uint2*)l;
}

// ---------------------------------------------------------------------------
// GEMM Y = A @ B^T, split-bf16 3-pass, cp.async 2-stage, 2 CTAs/SM.
// Pass order Ah*Bh -> Al*Bh -> Ah*Bl keeps al/bl never simultaneously live.
// MODE 0: fp32 row-major [GM][GN]; MODE 1: fp32 permuted [B,NH,T,HD];
// MODE 2: split-bf16 permuted (for V).
// ---------------------------------------------------------------------------
constexpr int BKG = 32;
constexpr int ROWB = 80;                         // 64B data + 16 pad
constexpr int TILE_BYTES  = 128 * ROWB;          // 10240
constexpr int STAGE_BYTES = 4 * TILE_BYTES;      // Ah, Al, Bh, Bl
constexpr int SMEM_GEMM   = 2 * STAGE_BYTES;     // 81920 -> 2 CTAs/SM
constexpr int NKB = GK / BKG;                    // 64

template <int MODE>
__global__ __launch_bounds__(256, 2) void gemm_mma_kernel(
    const __nv_bfloat16* __restrict__ Ah, const __nv_bfloat16* __restrict__ Al,
    const __nv_bfloat16* __restrict__ Bh, const __nv_bfloat16* __restrict__ Bl,
    float* __restrict__ Y, __nv_bfloat16* __restrict__ Yh,
    __nv_bfloat16* __restrict__ Yl)
{
    extern __shared__ char sm[];
    const uint32_t sb = smem_to_u32(sm);
    const int tid = threadIdx.x;
    const int wid = tid >> 5, lid = tid & 31;
    const int wm = wid & 1, wn = wid >> 1;
    const int bn = blockIdx.x * 128, bm = blockIdx.y * 128;
    const int lg = lid >> 3, li = lid & 7;

    float acc[4][4][4];
#pragma unroll
    for (int mt = 0; mt < 4; mt++)
#pragma unroll
        for (int nt = 0; nt < 4; nt++)
#pragma unroll
            for (int r = 0; r < 4; r++) acc[mt][nt][r] = 0.f;

    auto issue_stage = [&](int s, int kb) {
#pragma unroll
        for (int i = 0; i < 8; i++) {
            int f = tid + i * 256;
            int pl = f >> 9, rem = f & 511, row = rem >> 2, c = rem & 3;
            const __nv_bfloat16* sp = (pl == 0) ? Ah : (pl == 1) ? Al
                                     : (pl == 2) ? Bh : Bl;
            int rbase = (pl >= 2) ? bn : bm;
            cp_async16(sb + s * STAGE_BYTES + pl * TILE_BYTES + row * ROWB + c * 16,
                       sp + (size_t)(rbase + row) * GK + kb * BKG + c * 8);
        }
    };

    issue_stage(0, 0); CP_COMMIT();

    for (int kb = 0; kb < NKB; kb++) {
        CP_WAIT0();
        __syncthreads();                  // stage kb ready; prev compute done
        if (kb + 1 < NKB) { issue_stage((kb + 1) & 1, kb + 1); CP_COMMIT(); }

        const uint32_t st = sb + (kb & 1) * STAGE_BYTES;
        const uint32_t sAh = st, sAl = st + TILE_BYTES;
        const uint32_t sBh = st + 2 * TILE_BYTES, sBl = st + 3 * TILE_BYTES;

#pragma unroll
        for (int ks = 0; ks < 2; ks++) {
            const int ko = ks * 32;
            const int aoff = ((lg & 1) * 8 + li) * ROWB + ko + (lg >> 1) * 16;
            const int boff = ((lg >> 1) * 8 + li) * ROWB + ko + (lg & 1) * 16;

            uint32_t ah[4][4], bh[4][2];
#pragma unroll
            for (int mt = 0; mt < 4; mt++)
                ldmx4(ah[mt], sAh + (wm * 64 + mt * 16) * ROWB + aoff);
#pragma unroll
            for (int p = 0; p < 2; p++) {
                uint32_t r[4];
                ldmx4(r, sBh + (wn * 32 + p * 16) * ROWB + boff);
                bh[2*p][0] = r[0]; bh[2*p][1] = r[1];
                bh[2*p+1][0] = r[2]; bh[2*p+1][1] = r[3];
            }
            // pass 1: Ah x Bh
#pragma unroll
            for (int mt = 0; mt < 4; mt++)
#pragma unroll
                for (int nt = 0; nt < 4; nt++)
                    mma16816(acc[mt][nt], ah[mt], bh[nt]);
            // pass 2: Al x Bh (al live, bl not yet)
            {
                uint32_t al[4][4];
#pragma unroll
                for (int mt = 0; mt < 4; mt++)
                    ldmx4(al[mt], sAl + (wm * 64 + mt * 16) * ROWB + aoff);
#pragma unroll
                for (int mt = 0; mt < 4; mt++)
#pragma unroll
                    for (int nt = 0; nt < 4; nt++)
                        mma16816(acc[mt][nt], al[mt], bh[nt]);
            }
            // pass 3: Ah x Bl (bl live, al dead)
            {
                uint32_t bl[4][2];
#pragma unroll
                for (int p = 0; p < 2; p++) {
                    uint32_t r[4];
                    ldmx4(r, sBl + (wn * 32 + p * 16) * ROWB + boff);
                    bl[2*p][0] = r[0]; bl[2*p][1] = r[1];
                    bl[2*p+1][0] = r[2]; bl[2*p+1][1] = r[3];
                }
#pragma unroll
                for (int mt = 0; mt < 4; mt++)
#pragma unroll
                    for (int nt = 0; nt < 4; nt++)
                        mma16816(acc[mt][nt], ah[mt], bl[nt]);
            }
        }
    }

    const int er = lid >> 2;
    const int ec = (lid & 3) * 2;
#pragma unroll
    for (int mt = 0; mt < 4; mt++) {
#pragma unroll
        for (int half = 0; half < 2; half++) {
            int row = bm + wm * 64 + mt * 16 + half * 8 + er;
            size_t base;
            if (MODE == 0) {
                base = (size_t)row * GN + bn;
            } else {
                int b = row >> 11;
                int t = row & (CT - 1);
                int head = bn >> 7;
                base = (((size_t)b * CNH + head) * CT + t) * CHD;
            }
#pragma unroll
            for (int nt = 0; nt < 4; nt++) {
                int nc = wn * 32 + nt * 8 + ec;
                float v0 = acc[mt][nt][half * 2 + 0];
                float v1 = acc[mt][nt][half * 2 + 1];
                if (MODE == 2) {
                    __nv_bfloat162 h2 = __float22bfloat162_rn(make_float2(v0, v1));
                    *(uint32_t*)(Yh + base + nc) = *(uint32_t*)&h2;
                    float l0 = v0 - __bfloat162float(h2.x);
                    float l1 = v1 - __bfloat162float(h2.y);
                    *(uint32_t*)(Yl + base + nc) = pack_bf16(l0, l1);
                } else {
                    *(float2*)(Y + base + nc) = make_float2(v0, v1);
                }
            }
        }
    }
}

// ---------------------------------------------------------------------------
// RoPE + split: reads fp32 g_q/g_k, writes split bf16 (Q pre-scaled).
// ---------------------------------------------------------------------------
__global__ void rope_split_kernel(const float* __restrict__ cosb,
                                  const float* __restrict__ sinb)
{
    const float scale = 0.08838834764831843f;  // 1/sqrt(128)
    int idx = blockIdx.x * blockDim.x + threadIdx.x;   // < B*NH*T*64
    int d  = idx & 63;
    int t  = (idx >> 6) & (CT - 1);
    int bh = idx >> 17;
    size_t base = ((size_t)bh * CT + t) * CHD;
    float c0 = cosb[t * CHD + d],      c1 = cosb[t * CHD + d + 64];
    float s0 = sinb[t * CHD + d],      s1 = sinb[t * CHD + d + 64];
    float q0 = g_q[base + d], q1 = g_q[base + d + 64];
    float qa = fmaf(q0, c0, -q1 * s0) * scale;
    float qb = fmaf(q1, c1,  q0 * s1) * scale;
    float k0 = g_k[base + d], k1 = g_k[base + d + 64];
    float ka = fmaf(k0, c0, -k1 * s0);
    float kb = fmaf(k1, c1,  k0 * s1);
    __nv_bfloat16 h;
    h = __float2bfloat16(qa); g_qh[base + d] = h;
    g_ql[base + d] = __float2bfloat16(qa - __bfloat162float(h));
    h = __float2bfloat16(qb); g_qh[base + d + 64] = h;
    g_ql[base + d + 64] = __float2bfloat16(qb - __bfloat162float(h));
    h = __float2bfloat16(ka); g_kh[base + d] = h;
    g_kl[base + d] = __float2bfloat16(ka - __bfloat162float(h));
    h = __float2bfloat16(kb); g_kh[base + d + 64] = h;
    g_kl[base + d + 64] = __float2bfloat16(kb - __bfloat162float(h));
}

// ---------------------------------------------------------------------------
// Tensor-core flash attention (causal), split-bf16 3-pass for S and PV.
// qt REVERSED vs blockIdx.x so heavy diagonal tiles are scheduled FIRST
// (causal work ∝ qt+1; ascending launch order left the heavy tiles in the
// tail -> ~2x makespan).
// ---------------------------------------------------------------------------
constexpr int KROWB    = 272;                    // 256B data + 16 pad
constexpr int KV_PLANE = 64 * KROWB;             // 17408
constexpr int KV_STAGE = 4 * KV_PLANE;           // kh,kl,vh,vl
constexpr int SMEM_ATTN = 2 * KV_STAGE;          // 139264

__global__ __launch_bounds__(256) void attn_mma_kernel()
{
    extern __shared__ char sm[];
    const uint32_t sb = smem_to_u32(sm);
    const int qt = gridDim.x - 1 - blockIdx.x;   // heavy first
    const int h = blockIdx.y, b = blockIdx.z;
    const int tid = threadIdx.x, w = tid >> 5, l = tid & 31;
    const size_t bh = ((size_t)b * CNH + h) * CT * CHD;
    const int fr = l >> 2, t2 = (l & 3) * 2;     // frag row / col-pair base
    const int lg = l >> 3, li = l & 7;

    // --- Q hi fragments cached in registers (scaled upstream) ---
    const __nv_bfloat16* qhp = g_qh + bh + (size_t)(qt * 128 + w * 16) * CHD;
    const __nv_bfloat16* qlp = g_ql + bh + (size_t)(qt * 128 + w * 16) * CHD;
    uint32_t qhf[8][4];
#pragma unroll
    for (int ks = 0; ks < 8; ks++) {
        int c = ks * 16 + t2;
        qhf[ks][0] = *(const uint32_t*)(qhp + fr * 128 + c);
        qhf[ks][1] = *(const uint32_t*)(qhp + (fr + 8) * 128 + c);
        qhf[ks][2] = *(const uint32_t*)(qhp + fr * 128 + c + 8);
        qhf[ks][3] = *(const uint32_t*)(qhp + (fr + 8) * 128 + c + 8);
    }

    float o[16][4];
#pragma unroll
    for (int nt = 0; nt < 16; nt++)
#pragma unroll
        for (int e = 0; e < 4; e++) o[nt][e] = 0.f;
    float mx[2] = {-1e30f, -1e30f}, ls[2] = {0.f, 0.f};

    const int last = 2 * qt + 1;

    auto issue = [&](int s, int kt) {
        const __nv_bfloat16* srcs[4] = {
            g_kh + bh + (size_t)kt * 64 * CHD, g_kl + bh + (size_t)kt * 64 * CHD,
            g_vh + bh + (size_t)kt * 64 * CHD, g_vl + bh + (size_t)kt * 64 * CHD};
#pragma unroll
        for (int i = 0; i < 16; i++) {
            int f = tid + i * 256;
            int pl = f >> 10, rem = f & 1023, row = rem >> 4, c = rem & 15;
            cp_async16(sb + s * KV_STAGE + pl * KV_PLANE + row * KROWB + c * 16,
                       srcs[pl] + row * 128 + c * 8);
        }
    };

    issue(0, 0); CP_COMMIT();

    for (int kt = 0; kt <= last; kt++) {
        if (kt < last) { issue((kt + 1) & 1, kt + 1); CP_COMMIT(); CP_WAIT1(); }
        else           { CP_WAIT0(); }
        __syncthreads();

        const uint32_t st = sb + (kt & 1) * KV_STAGE;
        const uint32_t kh_s = st, kl_s = st + KV_PLANE;
        const uint32_t vh_s = st + 2 * KV_PLANE, vl_s = st + 3 * KV_PLANE;

        // ---- S = Qs @ K^T (3 passes) ----
        float s4[8][4];
#pragma unroll
        for (int nt = 0; nt < 8; nt++)
#pragma unroll
            for (int e = 0; e < 4; e++) s4[nt][e] = 0.f;

        const int boffb = ((lg >> 1) * 8 + li) * KROWB + (lg & 1) * 16;
#pragma unroll
        for (int ks = 0; ks < 8; ks++) {
            uint32_t bf[8][2];
#pragma unroll
            for (int p = 0; p < 4; p++) {
                uint32_t r[4];
                ldmx4(r, kh_s + p * 16 * KROWB + ks * 32 + boffb);
                bf[2*p][0] = r[0]; bf[2*p][1] = r[1];
                bf[2*p+1][0] = r[2]; bf[2*p+1][1] = r[3];
            }
#pragma unroll
            for (int nt = 0; nt < 8; nt++) mma16816(s4[nt], qhf[ks], bf[nt]);
            // Ql pass (fragments loaded from global, L1-resident)
            uint32_t qlf[4];
            int c = ks * 16 + t2;
            qlf[0] = *(const uint32_t*)(qlp + fr * 128 + c);
            qlf[1] = *(const uint32_t*)(qlp + (fr + 8) * 128 + c);
            qlf[2] = *(const uint32_t*)(qlp + fr * 128 + c + 8);
            qlf[3] = *(const uint32_t*)(qlp + (fr + 8) * 128 + c + 8);
#pragma unroll
            for (int nt = 0; nt < 8; nt++) mma16816(s4[nt], qlf, bf[nt]);
        }
#pragma unroll
        for (int ks = 0; ks < 8; ks++) {
            uint32_t bf[8][2];
#pragma unroll
            for (int p = 0; p < 4; p++) {
                uint32_t r[4];
                ldmx4(r, kl_s + p * 16 * KROWB + ks * 32 + boffb);
                bf[2*p][0] = r[0]; bf[2*p][1] = r[1];
                bf[2*p+1][0] = r[2]; bf[2*p+1][1] = r[3];
            }
#pragma unroll
            for (int nt = 0; nt < 8; nt++) mma16816(s4[nt], qhf[ks], bf[nt]);
        }

        // ---- causal mask (only the last two tiles can cross the diagonal) ----
        if (kt >= 2 * qt) {
            int row0 = qt * 128 + w * 16 + fr;
#pragma unroll
            for (int nt = 0; nt < 8; nt++) {
                int col0 = kt * 64 + nt * 8 + t2;
#pragma unroll
                for (int e = 0; e < 4; e++) {
                    int row = row0 + 8 * (e >> 1);
                    int col = col0 + (e & 1);
                    if (col > row) s4[nt][e] = -1e30f;
                }
            }
        }

        // ---- online softmax (rows fr, fr+8) ----
#pragma unroll
        for (int half = 0; half < 2; half++) {
            float rm = -1e30f;
#pragma unroll
            for (int nt = 0; nt < 8; nt++)
                rm = fmaxf(rm, fmaxf(s4[nt][2*half], s4[nt][2*half+1]));
            rm = fmaxf(rm, __shfl_xor_sync(0xffffffffu, rm, 1));
            rm = fmaxf(rm, __shfl_xor_sync(0xffffffffu, rm, 2));
            float mn = fmaxf(mx[half], rm);
            float al = __expf(mx[half] - mn);
            mx[half] = mn;
            float rs = 0.f;
#pragma unroll
            for (int nt = 0; nt < 8; nt++) {
                s4[nt][2*half]   = __expf(s4[nt][2*half]   - mn);
                s4[nt][2*half+1] = __expf(s4[nt][2*half+1] - mn);
                rs += s4[nt][2*half] + s4[nt][2*half+1];
            }
            rs += __shfl_xor_sync(0xffffffffu, rs, 1);
            rs += __shfl_xor_sync(0xffffffffu, rs, 2);
            ls[half] = ls[half] * al + rs;
#pragma unroll
            for (int nt = 0; nt < 16; nt++) {
                o[nt][2*half]   *= al;
                o[nt][2*half+1] *= al;
            }
        }

        // ---- P fragments (hi/lo) directly from S fragments ----
        uint32_t pha[4][4], pla[4][4];
#pragma unroll
        for (int kc = 0; kc < 4; kc++) {
#pragma unroll
            for (int j = 0; j < 4; j++) {
                int nt = 2 * kc + (j >> 1);
                int eb = (j & 1) * 2;
                float x0 = s4[nt][eb], x1 = s4[nt][eb + 1];
                __nv_bfloat162 h2 = __float22bfloat162_rn(make_float2(x0, x1));
                pha[kc][j] = *(uint32_t*)&h2;
                pla[kc][j] = pack_bf16(x0 - __bfloat162float(h2.x),
                                       x1 - __bfloat162float(h2.y));
            }
        }

        // ---- O += P @ V (3 passes) ----
#pragma unroll
        for (int kc = 0; kc < 4; kc++) {
            uint32_t vb[16][2];
#pragma unroll
            for (int p = 0; p < 8; p++) {
                uint32_t r[4];
                uint32_t addr = vh_s + (kc * 16 + (lg & 1) * 8 + li) * KROWB
                                + (p * 16 + (lg >> 1) * 8) * 2;
                ldmx4t(r, addr);
                vb[2*p][0] = r[0]; vb[2*p][1] = r[1];
                vb[2*p+1][0] = r[2]; vb[2*p+1][1] = r[3];
            }
#pragma unroll
            for (int nt = 0; nt < 16; nt++) mma16816(o[nt], pha[kc], vb[nt]);
#pragma unroll
            for (int nt = 0; nt < 16; nt++) mma16816(o[nt], pla[kc], vb[nt]);
#pragma unroll
            for (int p = 0; p < 8; p++) {
                uint32_t r[4];
                uint32_t addr = vl_s + (kc * 16 + (lg & 1) * 8 + li) * KROWB
                                + (p * 16 + (lg >> 1) * 8) * 2;
                ldmx4t(r, addr);
                vb[2*p][0] = r[0]; vb[2*p][1] = r[1];
                vb[2*p+1][0] = r[2]; vb[2*p+1][1] = r[3];
            }
#pragma unroll
            for (int nt = 0; nt < 16; nt++) mma16816(o[nt], pha[kc], vb[nt]);
        }
        __syncthreads();   // all warps done with this stage before reuse
    }

    // ---- epilogue: O /= l; write split-bf16 [B*T][H] ----
    float inv0 = 1.f / ls[0], inv1 = 1.f / ls[1];
    int row0 = qt * 128 + w * 16 + fr;
    size_t r0 = ((size_t)b * CT + row0) * CH + h * CHD;
    size_t r1 = ((size_t)b * CT + row0 + 8) * CH + h * CHD;
#pragma unroll
    for (int nt = 0; nt < 16; nt++) {
        int col = nt * 8 + t2;
        float v0 = o[nt][0] * inv0, v1 = o[nt][1] * inv0;
        __nv_bfloat162 h2 = __float22bfloat162_rn(make_float2(v0, v1));
        *(uint32_t*)(g_aoh + r0 + col) = *(uint32_t*)&h2;
        *(uint32_t*)(g_aol + r0 + col) =
            pack_bf16(v0 - __bfloat162float(h2.x), v1 - __bfloat162float(h2.y));
        float v2 = o[nt][2] * inv1, v3 = o[nt][3] * inv1;
        __nv_bfloat162 h3 = __float22bfloat162_rn(make_float2(v2, v3));
        *(uint32_t*)(g_aoh + r1 + col) = *(uint32_t*)&h3;
        *(uint32_t*)(g_aol + r1 + col) =
            pack_bf16(v2 - __bfloat162float(h3.x), v3 - __bfloat162float(h3.y));
    }
}

// ---------------------------------------------------------------------------
// Launch
// ---------------------------------------------------------------------------
extern "C" void kernel_launch(void* const* d_in, const int* in_sizes, int n_in,
                              void* d_out, int out_size)
{
    (void)in_sizes; (void)n_in; (void)out_size;
    const float* x    = (const float*)d_in[0];
    const float* cosb = (const float*)d_in[1];
    const float* sinb = (const float*)d_in[2];
    const float* Wq   = (const float*)d_in[3];
    const float* Wk   = (const float*)d_in[4];
    const float* Wv   = (const float*)d_in[5];
    const float* Wo   = (const float*)d_in[6];
    float* out = (float*)d_out;

    float *qp, *kp;
    cudaGetSymbolAddress((void**)&qp, g_q);
    cudaGetSymbolAddress((void**)&kp, g_k);
    __nv_bfloat16 *xh, *xl, *wh, *wl, *vh, *vl, *aoh, *aol;
    cudaGetSymbolAddress((void**)&xh,  g_xh);
    cudaGetSymbolAddress((void**)&xl,  g_xl);
    cudaGetSymbolAddress((void**)&wh,  g_wh);
    cudaGetSymbolAddress((void**)&wl,  g_wl);
    cudaGetSymbolAddress((void**)&vh,  g_vh);
    cudaGetSymbolAddress((void**)&vl,  g_vl);
    cudaGetSymbolAddress((void**)&aoh, g_aoh);
    cudaGetSymbolAddress((void**)&aol, g_aol);

    cudaFuncSetAttribute(attn_mma_kernel,
                         cudaFuncAttributeMaxDynamicSharedMemorySize, SMEM_ATTN);
    cudaFuncSetAttribute(gemm_mma_kernel<0>,
                         cudaFuncAttributeMaxDynamicSharedMemorySize, SMEM_GEMM);
    cudaFuncSetAttribute(gemm_mma_kernel<1>,
                         cudaFuncAttributeMaxDynamicSharedMemorySize, SMEM_GEMM);
    cudaFuncSetAttribute(gemm_mma_kernel<2>,
                         cudaFuncAttributeMaxDynamicSharedMemorySize, SMEM_GEMM);

    const size_t WSZ = (size_t)GN * GK;
    const int n4x = GM * GK / 4;
    const int n4w = GN * GK / 4;

    cvt_split_kernel<<<(n4x + 255) / 256, 256>>>(x,  xh, xl, n4x);
    cvt_split_kernel<<<(n4w + 255) / 256, 256>>>(Wq, wh + 0 * WSZ, wl + 0 * WSZ, n4w);
    cvt_split_kernel<<<(n4w + 255) / 256, 256>>>(Wk, wh + 1 * WSZ, wl + 1 * WSZ, n4w);
    cvt_split_kernel<<<(n4w + 255) / 256, 256>>>(Wv, wh + 2 * WSZ, wl + 2 * WSZ, n4w);
    cvt_split_kernel<<<(n4w + 255) / 256, 256>>>(Wo, wh + 3 * WSZ, wl + 3 * WSZ, n4w);

    dim3 gg(GN / 128, GM / 128);  // (16, 32)
    gemm_mma_kernel<1><<<gg, 256, SMEM_GEMM>>>(xh, xl, wh + 0 * WSZ, wl + 0 * WSZ,
                                               qp, nullptr, nullptr);
    gemm_mma_kernel<1><<<gg, 256, SMEM_GEMM>>>(xh, xl, wh + 1 * WSZ, wl + 1 * WSZ,
                                               kp, nullptr, nullptr);
    gemm_mma_kernel<2><<<gg, 256, SMEM_GEMM>>>(xh, xl, wh + 2 * WSZ, wl + 2 * WSZ,
                                               nullptr, vh, vl);

    rope_split_kernel<<<(CB * CNH * CT * 64) / 256, 256>>>(cosb, sinb);
    attn_mma_kernel<<<dim3(CT / 128, CNH, CB), 256, SMEM_ATTN>>>();

    gemm_mma_kernel<0><<<gg, 256, SMEM_GEMM>>>(aoh, aol, wh + 3 * WSZ, wl + 3 * WSZ,
                                               out, nullptr, nullptr);
}

// round 10
// speedup vs baseline: 2.7054x; 1.0177x over previous
#include <cuda_runtime.h>
#include <cuda_bf16.h>
#include <cstdint>
#include <math.h>

// Problem constants
constexpr int CB  = 2;     // batch
constexpr int CT  = 2048;  // seq len
constexpr int CH  = 2048;  // hidden
constexpr int CNH = 16;    // heads
constexpr int CHD = 128;   // head dim
constexpr int GM  = CB * CT;   // 4096
constexpr int GK  = CH;        // 2048
constexpr int GN  = CH;        // 2048

// ---------------------------------------------------------------------------
// Scratch (allocation-free: __device__ globals)
// ---------------------------------------------------------------------------
__device__ float g_q [(size_t)CB * CNH * CT * CHD];  // fp32 Q pre-RoPE [B,NH,T,HD]
__device__ float g_k [(size_t)CB * CNH * CT * CHD];

// split-bf16 planes
__device__ __align__(16) __nv_bfloat16 g_xh [(size_t)GM * GK];
__device__ __align__(16) __nv_bfloat16 g_xl [(size_t)GM * GK];
__device__ __align__(16) __nv_bfloat16 g_wh [4][(size_t)GN * GK];  // q,k,v,o
__device__ __align__(16) __nv_bfloat16 g_wl [4][(size_t)GN * GK];
__device__ __align__(16) __nv_bfloat16 g_qh [(size_t)CB * CNH * CT * CHD];  // scaled
__device__ __align__(16) __nv_bfloat16 g_ql [(size_t)CB * CNH * CT * CHD];
__device__ __align__(16) __nv_bfloat16 g_kh [(size_t)CB * CNH * CT * CHD];
__device__ __align__(16) __nv_bfloat16 g_kl [(size_t)CB * CNH * CT * CHD];
__device__ __align__(16) __nv_bfloat16 g_vh [(size_t)CB * CNH * CT * CHD];
__device__ __align__(16) __nv_bfloat16 g_vl [(size_t)CB * CNH * CT * CHD];
__device__ __align__(16) __nv_bfloat16 g_aoh[(size_t)GM * GK];  // attn out [B*T][H]
__device__ __align__(16) __nv_bfloat16 g_aol[(size_t)GM * GK];

// ---------------------------------------------------------------------------
// Baseline-ISA helpers (all valid on compute_103 virtual arch)
// ---------------------------------------------------------------------------
__device__ __forceinline__ uint32_t smem_to_u32(const void* p) {
    uint32_t a;
    asm("{ .reg .u64 t; cvta.to.shared.u64 t, %1; cvt.u32.u64 %0, t; }"
        : "=r"(a) : "l"(p));
    return a;
}
__device__ __forceinline__ void ldmx4(uint32_t* r, uint32_t addr) {
    asm volatile("ldmatrix.sync.aligned.m8n8.x4.shared.b16 {%0,%1,%2,%3}, [%4];"
        : "=r"(r[0]), "=r"(r[1]), "=r"(r[2]), "=r"(r[3]) : "r"(addr));
}
__device__ __forceinline__ void ldmx4t(uint32_t* r, uint32_t addr) {
    asm volatile("ldmatrix.sync.aligned.m8n8.x4.trans.shared.b16 {%0,%1,%2,%3}, [%4];"
        : "=r"(r[0]), "=r"(r[1]), "=r"(r[2]), "=r"(r[3]) : "r"(addr));
}
__device__ __forceinline__ void mma16816(float* d, const uint32_t* a,
                                         const uint32_t* b) {
    asm volatile(
        "mma.sync.aligned.m16n8k16.row.col.f32.bf16.bf16.f32 "
        "{%0,%1,%2,%3}, {%4,%5,%6,%7}, {%8,%9}, {%0,%1,%2,%3};"
        : "+f"(d[0]), "+f"(d[1]), "+f"(d[2]), "+f"(d[3])
        : "r"(a[0]), "r"(a[1]), "r"(a[2]), "r"(a[3]), "r"(b[0]), "r"(b[1]));
}
__device__ __forceinline__ void cp_async16(uint32_t dst, const void* src) {
    asm volatile("cp.async.cg.shared.global [%0], [%1], 16;"
        :: "r"(dst), "l"(src));
}
#define CP_COMMIT() asm volatile("cp.async.commit_group;" ::: "memory")
#define CP_WAIT0()  asm volatile("cp.async.wait_group 0;" ::: "memory")

__device__ __forceinline__ uint32_t pack_bf16(float a, float b) {
    __nv_bfloat162 h = __float22bfloat162_rn(make_float2(a, b));
    return *(uint32_t*)&h;
}

// ---------------------------------------------------------------------------
// Split conversion: hi = bf16(x), lo = bf16(x - hi)
// ---------------------------------------------------------------------------
__global__ void cvt_split_kernel(const float* __restrict__ src,
                                 __nv_bfloat16* __restrict__ hi,
                                 __nv_bfloat16* __restrict__ lo, int n4)
{
    int i = blockIdx.x * blockDim.x + threadIdx.x;
    if (i >= n4) return;
    float4 v = ((const float4*)src)[i];
    __nv_bfloat16 h[4], l[4];
    h[0] = __float2bfloat16(v.x); l[0] = __float2bfloat16(v.x - __bfloat162float(h[0]));
    h[1] = __float2bfloat16(v.y); l[1] = __float2bfloat16(v.y - __bfloat162float(h[1]));
    h[2] = __float2bfloat16(v.z); l[2] = __float2bfloat16(v.z - __bfloat162float(h[2]));
    h[3] = __float2bfloat16(v.w); l[3] = __float2bfloat16(v.w - __bfloat162float(h[3]));
    *(uint2*)(hi + (size_t)i * 4) = *(uint2*)h;
    *(uint2*)(lo + (size_t)i * 4) = *(uint2*)l;
}

// ---------------------------------------------------------------------------
// GEMM Y = A @ B^T, split-bf16 3-pass, cp.async 2-stage, 2 CTAs/SM.
// ---------------------------------------------------------------------------
constexpr int BKG = 32;
constexpr int ROWB = 80;                         // 64B data + 16 pad
constexpr int TILE_BYTES  = 128 * ROWB;          // 10240
constexpr int STAGE_BYTES = 4 * TILE_BYTES;      // Ah, Al, Bh, Bl
constexpr int SMEM_GEMM   = 2 * STAGE_BYTES;     // 81920 -> 2 CTAs/SM
constexpr int NKB = GK / BKG;                    // 64

template <int MODE>
__global__ __launch_bounds__(256, 2) void gemm_mma_kernel(
    const __nv_bfloat16* __restrict__ Ah, const __nv_bfloat16* __restrict__ Al,
    const __nv_bfloat16* __restrict__ Bh, const __nv_bfloat16* __restrict__ Bl,
    float* __restrict__ Y, __nv_bfloat16* __restrict__ Yh,
    __nv_bfloat16* __restrict__ Yl)
{
    extern __shared__ char sm[];
    const uint32_t sb = smem_to_u32(sm);
    const int tid = threadIdx.x;
    const int wid = tid >> 5, lid = tid & 31;
    const int wm = wid & 1, wn = wid >> 1;
    const int bn = blockIdx.x * 128, bm = blockIdx.y * 128;
    const int lg = lid >> 3, li = lid & 7;

    float acc[4][4][4];
#pragma unroll
    for (int mt = 0; mt < 4; mt++)
#pragma unroll
        for (int nt = 0; nt < 4; nt++)
#pragma unroll
            for (int r = 0; r < 4; r++) acc[mt][nt][r] = 0.f;

    auto issue_stage = [&](int s, int kb) {
#pragma unroll
        for (int i = 0; i < 8; i++) {
            int f = tid + i * 256;
            int pl = f >> 9, rem = f & 511, row = rem >> 2, c = rem & 3;
            const __nv_bfloat16* sp = (pl == 0) ? Ah : (pl == 1) ? Al
                                     : (pl == 2) ? Bh : Bl;
            int rbase = (pl >= 2) ? bn : bm;
            cp_async16(sb + s * STAGE_BYTES + pl * TILE_BYTES + row * ROWB + c * 16,
                       sp + (size_t)(rbase + row) * GK + kb * BKG + c * 8);
        }
    };

    issue_stage(0, 0); CP_COMMIT();

    for (int kb = 0; kb < NKB; kb++) {
        CP_WAIT0();
        __syncthreads();                  // stage kb ready; prev compute done
        if (kb + 1 < NKB) { issue_stage((kb + 1) & 1, kb + 1); CP_COMMIT(); }

        const uint32_t st = sb + (kb & 1) * STAGE_BYTES;
        const uint32_t sAh = st, sAl = st + TILE_BYTES;
        const uint32_t sBh = st + 2 * TILE_BYTES, sBl = st + 3 * TILE_BYTES;

#pragma unroll
        for (int ks = 0; ks < 2; ks++) {
            const int ko = ks * 32;
            const int aoff = ((lg & 1) * 8 + li) * ROWB + ko + (lg >> 1) * 16;
            const int boff = ((lg >> 1) * 8 + li) * ROWB + ko + (lg & 1) * 16;

            uint32_t ah[4][4], bh[4][2];
#pragma unroll
            for (int mt = 0; mt < 4; mt++)
                ldmx4(ah[mt], sAh + (wm * 64 + mt * 16) * ROWB + aoff);
#pragma unroll
            for (int p = 0; p < 2; p++) {
                uint32_t r[4];
                ldmx4(r, sBh + (wn * 32 + p * 16) * ROWB + boff);
                bh[2*p][0] = r[0]; bh[2*p][1] = r[1];
                bh[2*p+1][0] = r[2]; bh[2*p+1][1] = r[3];
            }
            // pass 1: Ah x Bh
#pragma unroll
            for (int mt = 0; mt < 4; mt++)
#pragma unroll
                for (int nt = 0; nt < 4; nt++)
                    mma16816(acc[mt][nt], ah[mt], bh[nt]);
            // pass 2: Al x Bh
            {
                uint32_t al[4][4];
#pragma unroll
                for (int mt = 0; mt < 4; mt++)
                    ldmx4(al[mt], sAl + (wm * 64 + mt * 16) * ROWB + aoff);
#pragma unroll
                for (int mt = 0; mt < 4; mt++)
#pragma unroll
                    for (int nt = 0; nt < 4; nt++)
                        mma16816(acc[mt][nt], al[mt], bh[nt]);
            }
            // pass 3: Ah x Bl
            {
                uint32_t bl[4][2];
#pragma unroll
                for (int p = 0; p < 2; p++) {
                    uint32_t r[4];
                    ldmx4(r, sBl + (wn * 32 + p * 16) * ROWB + boff);
                    bl[2*p][0] = r[0]; bl[2*p][1] = r[1];
                    bl[2*p+1][0] = r[2]; bl[2*p+1][1] = r[3];
                }
#pragma unroll
                for (int mt = 0; mt < 4; mt++)
#pragma unroll
                    for (int nt = 0; nt < 4; nt++)
                        mma16816(acc[mt][nt], ah[mt], bl[nt]);
            }
        }
    }

    const int er = lid >> 2;
    const int ec = (lid & 3) * 2;
#pragma unroll
    for (int mt = 0; mt < 4; mt++) {
#pragma unroll
        for (int half = 0; half < 2; half++) {
            int row = bm + wm * 64 + mt * 16 + half * 8 + er;
            size_t base;
            if (MODE == 0) {
                base = (size_t)row * GN + bn;
            } else {
                int b = row >> 11;
                int t = row & (CT - 1);
                int head = bn >> 7;
                base = (((size_t)b * CNH + head) * CT + t) * CHD;
            }
#pragma unroll
            for (int nt = 0; nt < 4; nt++) {
                int nc = wn * 32 + nt * 8 + ec;
                float v0 = acc[mt][nt][half * 2 + 0];
                float v1 = acc[mt][nt][half * 2 + 1];
                if (MODE == 2) {
                    __nv_bfloat162 h2 = __float22bfloat162_rn(make_float2(v0, v1));
                    *(uint32_t*)(Yh + base + nc) = *(uint32_t*)&h2;
                    float l0 = v0 - __bfloat162float(h2.x);
                    float l1 = v1 - __bfloat162float(h2.y);
                    *(uint32_t*)(Yl + base + nc) = pack_bf16(l0, l1);
                } else {
                    *(float2*)(Y + base + nc) = make_float2(v0, v1);
                }
            }
        }
    }
}

// ---------------------------------------------------------------------------
// RoPE + split: reads fp32 g_q/g_k, writes split bf16 (Q pre-scaled).
// ---------------------------------------------------------------------------
__global__ void rope_split_kernel(const float* __restrict__ cosb,
                                  const float* __restrict__ sinb)
{
    const float scale = 0.08838834764831843f;  // 1/sqrt(128)
    int idx = blockIdx.x * blockDim.x + threadIdx.x;   // < B*NH*T*64
    int d  = idx & 63;
    int t  = (idx >> 6) & (CT - 1);
    int bh = idx >> 17;
    size_t base = ((size_t)bh * CT + t) * CHD;
    float c0 = cosb[t * CHD + d],      c1 = cosb[t * CHD + d + 64];
    float s0 = sinb[t * CHD + d],      s1 = sinb[t * CHD + d + 64];
    float q0 = g_q[base + d], q1 = g_q[base + d + 64];
    float qa = fmaf(q0, c0, -q1 * s0) * scale;
    float qb = fmaf(q1, c1,  q0 * s1) * scale;
    float k0 = g_k[base + d], k1 = g_k[base + d + 64];
    float ka = fmaf(k0, c0, -k1 * s0);
    float kb = fmaf(k1, c1,  k0 * s1);
    __nv_bfloat16 h;
    h = __float2bfloat16(qa); g_qh[base + d] = h;
    g_ql[base + d] = __float2bfloat16(qa - __bfloat162float(h));
    h = __float2bfloat16(qb); g_qh[base + d + 64] = h;
    g_ql[base + d + 64] = __float2bfloat16(qb - __bfloat162float(h));
    h = __float2bfloat16(ka); g_kh[base + d] = h;
    g_kl[base + d] = __float2bfloat16(ka - __bfloat162float(h));
    h = __float2bfloat16(kb); g_kh[base + d + 64] = h;
    g_kl[base + d + 64] = __float2bfloat16(kb - __bfloat162float(h));
}

// ---------------------------------------------------------------------------
// Tensor-core flash attention (causal). qt reversed (heavy first).
// Loop restructured: wait -> ONE sync -> issue next -> compute. The old
// end-of-loop barrier is redundant in this shape (after the top barrier all
// warps finished kt-1, so overwriting kt-1's buffer is safe).
// ---------------------------------------------------------------------------
constexpr int KROWB    = 272;                    // 256B data + 16 pad
constexpr int KV_PLANE = 64 * KROWB;             // 17408
constexpr int KV_STAGE = 4 * KV_PLANE;           // kh,kl,vh,vl
constexpr int SMEM_ATTN = 2 * KV_STAGE;          // 139264

__global__ __launch_bounds__(256) void attn_mma_kernel()
{
    extern __shared__ char sm[];
    const uint32_t sb = smem_to_u32(sm);
    const int qt = gridDim.x - 1 - blockIdx.x;   // heavy first
    const int h = blockIdx.y, b = blockIdx.z;
    const int tid = threadIdx.x, w = tid >> 5, l = tid & 31;
    const size_t bh = ((size_t)b * CNH + h) * CT * CHD;
    const int fr = l >> 2, t2 = (l & 3) * 2;
    const int lg = l >> 3, li = l & 7;

    const __nv_bfloat16* qhp = g_qh + bh + (size_t)(qt * 128 + w * 16) * CHD;
    const __nv_bfloat16* qlp = g_ql + bh + (size_t)(qt * 128 + w * 16) * CHD;
    uint32_t qhf[8][4];
#pragma unroll
    for (int ks = 0; ks < 8; ks++) {
        int c = ks * 16 + t2;
        qhf[ks][0] = *(const uint32_t*)(qhp + fr * 128 + c);
        qhf[ks][1] = *(const uint32_t*)(qhp + (fr + 8) * 128 + c);
        qhf[ks][2] = *(const uint32_t*)(qhp + fr * 128 + c + 8);
        qhf[ks][3] = *(const uint32_t*)(qhp + (fr + 8) * 128 + c + 8);
    }

    float o[16][4];
#pragma unroll
    for (int nt = 0; nt < 16; nt++)
#pragma unroll
        for (int e = 0; e < 4; e++) o[nt][e] = 0.f;
    float mx[2] = {-1e30f, -1e30f}, ls[2] = {0.f, 0.f};

    const int last = 2 * qt + 1;

    auto issue = [&](int s, int kt) {
        const __nv_bfloat16* srcs[4] = {
            g_kh + bh + (size_t)kt * 64 * CHD, g_kl + bh + (size_t)kt * 64 * CHD,
            g_vh + bh + (size_t)kt * 64 * CHD, g_vl + bh + (size_t)kt * 64 * CHD};
#pragma unroll
        for (int i = 0; i < 16; i++) {
            int f = tid + i * 256;
            int pl = f >> 10, rem = f & 1023, row = rem >> 4, c = rem & 15;
            cp_async16(sb + s * KV_STAGE + pl * KV_PLANE + row * KROWB + c * 16,
                       srcs[pl] + row * 128 + c * 8);
        }
    };

    issue(0, 0); CP_COMMIT();

    for (int kt = 0; kt <= last; kt++) {
        CP_WAIT0();
        __syncthreads();           // stage kt visible; all warps done with kt-1
        if (kt < last) { issue((kt + 1) & 1, kt + 1); CP_COMMIT(); }

        const uint32_t st = sb + (kt & 1) * KV_STAGE;
        const uint32_t kh_s = st, kl_s = st + KV_PLANE;
        const uint32_t vh_s = st + 2 * KV_PLANE, vl_s = st + 3 * KV_PLANE;

        // ---- S = Qs @ K^T (3 passes) ----
        float s4[8][4];
#pragma unroll
        for (int nt = 0; nt < 8; nt++)
#pragma unroll
            for (int e = 0; e < 4; e++) s4[nt][e] = 0.f;

        const int boffb = ((lg >> 1) * 8 + li) * KROWB + (lg & 1) * 16;
#pragma unroll
        for (int ks = 0; ks < 8; ks++) {
            uint32_t bf[8][2];
#pragma unroll
            for (int p = 0; p < 4; p++) {
                uint32_t r[4];
                ldmx4(r, kh_s + p * 16 * KROWB + ks * 32 + boffb);
                bf[2*p][0] = r[0]; bf[2*p][1] = r[1];
                bf[2*p+1][0] = r[2]; bf[2*p+1][1] = r[3];
            }
#pragma unroll
            for (int nt = 0; nt < 8; nt++) mma16816(s4[nt], qhf[ks], bf[nt]);
            uint32_t qlf[4];
            int c = ks * 16 + t2;
            qlf[0] = *(const uint32_t*)(qlp + fr * 128 + c);
            qlf[1] = *(const uint32_t*)(qlp + (fr + 8) * 128 + c);
            qlf[2] = *(const uint32_t*)(qlp + fr * 128 + c + 8);
            qlf[3] = *(const uint32_t*)(qlp + (fr + 8) * 128 + c + 8);
#pragma unroll
            for (int nt = 0; nt < 8; nt++) mma16816(s4[nt], qlf, bf[nt]);
        }
#pragma unroll
        for (int ks = 0; ks < 8; ks++) {
            uint32_t bf[8][2];
#pragma unroll
            for (int p = 0; p < 4; p++) {
                uint32_t r[4];
                ldmx4(r, kl_s + p * 16 * KROWB + ks * 32 + boffb);
                bf[2*p][0] = r[0]; bf[2*p][1] = r[1];
                bf[2*p+1][0] = r[2]; bf[2*p+1][1] = r[3];
            }
#pragma unroll
            for (int nt = 0; nt < 8; nt++) mma16816(s4[nt], qhf[ks], bf[nt]);
        }

        // ---- causal mask ----
        if (kt >= 2 * qt) {
            int row0 = qt * 128 + w * 16 + fr;
#pragma unroll
            for (int nt = 0; nt < 8; nt++) {
                int col0 = kt * 64 + nt * 8 + t2;
#pragma unroll
                for (int e = 0; e < 4; e++) {
                    int row = row0 + 8 * (e >> 1);
                    int col = col0 + (e & 1);
                    if (col > row) s4[nt][e] = -1e30f;
                }
            }
        }

        // ---- online softmax ----
#pragma unroll
        for (int half = 0; half < 2; half++) {
            float rm = -1e30f;
#pragma unroll
            for (int nt = 0; nt < 8; nt++)
                rm = fmaxf(rm, fmaxf(s4[nt][2*half], s4[nt][2*half+1]));
            rm = fmaxf(rm, __shfl_xor_sync(0xffffffffu, rm, 1));
            rm = fmaxf(rm, __shfl_xor_sync(0xffffffffu, rm, 2));
            float mn = fmaxf(mx[half], rm);
            float al = __expf(mx[half] - mn);
            mx[half] = mn;
            float rs = 0.f;
#pragma unroll
            for (int nt = 0; nt < 8; nt++) {
                s4[nt][2*half]   = __expf(s4[nt][2*half]   - mn);
                s4[nt][2*half+1] = __expf(s4[nt][2*half+1] - mn);
                rs += s4[nt][2*half] + s4[nt][2*half+1];
            }
            rs += __shfl_xor_sync(0xffffffffu, rs, 1);
            rs += __shfl_xor_sync(0xffffffffu, rs, 2);
            ls[half] = ls[half] * al + rs;
#pragma unroll
            for (int nt = 0; nt < 16; nt++) {
                o[nt][2*half]   *= al;
                o[nt][2*half+1] *= al;
            }
        }

        // ---- P fragments (hi/lo) ----
        uint32_t pha[4][4], pla[4][4];
#pragma unroll
        for (int kc = 0; kc < 4; kc++) {
#pragma unroll
            for (int j = 0; j < 4; j++) {
                int nt = 2 * kc + (j >> 1);
                int eb = (j & 1) * 2;
                float x0 = s4[nt][eb], x1 = s4[nt][eb + 1];
                __nv_bfloat162 h2 = __float22bfloat162_rn(make_float2(x0, x1));
                pha[kc][j] = *(uint32_t*)&h2;
                pla[kc][j] = pack_bf16(x0 - __bfloat162float(h2.x),
                                       x1 - __bfloat162float(h2.y));
            }
        }

        // ---- O += P @ V (3 passes) ----
#pragma unroll
        for (int kc = 0; kc < 4; kc++) {
            uint32_t vb[16][2];
#pragma unroll
            for (int p = 0; p < 8; p++) {
                uint32_t r[4];
                uint32_t addr = vh_s + (kc * 16 + (lg & 1) * 8 + li) * KROWB
                                + (p * 16 + (lg >> 1) * 8) * 2;
                ldmx4t(r, addr);
                vb[2*p][0] = r[0]; vb[2*p][1] = r[1];
                vb[2*p+1][0] = r[2]; vb[2*p+1][1] = r[3];
            }
#pragma unroll
            for (int nt = 0; nt < 16; nt++) mma16816(o[nt], pha[kc], vb[nt]);
#pragma unroll
            for (int nt = 0; nt < 16; nt++) mma16816(o[nt], pla[kc], vb[nt]);
#pragma unroll
            for (int p = 0; p < 8; p++) {
                uint32_t r[4];
                uint32_t addr = vl_s + (kc * 16 + (lg & 1) * 8 + li) * KROWB
                                + (p * 16 + (lg >> 1) * 8) * 2;
                ldmx4t(r, addr);
                vb[2*p][0] = r[0]; vb[2*p][1] = r[1];
                vb[2*p+1][0] = r[2]; vb[2*p+1][1] = r[3];
            }
#pragma unroll
            for (int nt = 0; nt < 16; nt++) mma16816(o[nt], pha[kc], vb[nt]);
        }
    }

    // ---- epilogue ----
    float inv0 = 1.f / ls[0], inv1 = 1.f / ls[1];
    int row0 = qt * 128 + w * 16 + fr;
    size_t r0 = ((size_t)b * CT + row0) * CH + h * CHD;
    size_t r1 = ((size_t)b * CT + row0 + 8) * CH + h * CHD;
#pragma unroll
    for (int nt = 0; nt < 16; nt++) {
        int col = nt * 8 + t2;
        float v0 = o[nt][0] * inv0, v1 = o[nt][1] * inv0;
        __nv_bfloat162 h2 = __float22bfloat162_rn(make_float2(v0, v1));
        *(uint32_t*)(g_aoh + r0 + col) = *(uint32_t*)&h2;
        *(uint32_t*)(g_aol + r0 + col) =
            pack_bf16(v0 - __bfloat162float(h2.x), v1 - __bfloat162float(h2.y));
        float v2 = o[nt][2] * inv1, v3 = o[nt][3] * inv1;
        __nv_bfloat162 h3 = __float22bfloat162_rn(make_float2(v2, v3));
        *(uint32_t*)(g_aoh + r1 + col) = *(uint32_t*)&h3;
        *(uint32_t*)(g_aol + r1 + col) =
            pack_bf16(v2 - __bfloat162float(h3.x), v3 - __bfloat162float(h3.y));
    }
}

// ---------------------------------------------------------------------------
// Launch — fork-join side streams so independent prologue work overlaps.
// Streams/events created lazily ONCE (host objects only; no device alloc).
// ---------------------------------------------------------------------------
extern "C" void kernel_launch(void* const* d_in, const int* in_sizes, int n_in,
                              void* d_out, int out_size)
{
    (void)in_sizes; (void)n_in; (void)out_size;
    const float* x    = (const float*)d_in[0];
    const float* cosb = (const float*)d_in[1];
    const float* sinb = (const float*)d_in[2];
    const float* Wq   = (const float*)d_in[3];
    const float* Wk   = (const float*)d_in[4];
    const float* Wv   = (const float*)d_in[5];
    const float* Wo   = (const float*)d_in[6];
    float* out = (float*)d_out;

    float *qp, *kp;
    cudaGetSymbolAddress((void**)&qp, g_q);
    cudaGetSymbolAddress((void**)&kp, g_k);
    __nv_bfloat16 *xh, *xl, *wh, *wl, *vh, *vl, *aoh, *aol;
    cudaGetSymbolAddress((void**)&xh,  g_xh);
    cudaGetSymbolAddress((void**)&xl,  g_xl);
    cudaGetSymbolAddress((void**)&wh,  g_wh);
    cudaGetSymbolAddress((void**)&wl,  g_wl);
    cudaGetSymbolAddress((void**)&vh,  g_vh);
    cudaGetSymbolAddress((void**)&vl,  g_vl);
    cudaGetSymbolAddress((void**)&aoh, g_aoh);
    cudaGetSymbolAddress((void**)&aol, g_aol);

    cudaFuncSetAttribute(attn_mma_kernel,
                         cudaFuncAttributeMaxDynamicSharedMemorySize, SMEM_ATTN);
    cudaFuncSetAttribute(gemm_mma_kernel<0>,
                         cudaFuncAttributeMaxDynamicSharedMemorySize, SMEM_GEMM);
    cudaFuncSetAttribute(gemm_mma_kernel<1>,
                         cudaFuncAttributeMaxDynamicSharedMemorySize, SMEM_GEMM);
    cudaFuncSetAttribute(gemm_mma_kernel<2>,
                         cudaFuncAttributeMaxDynamicSharedMemorySize, SMEM_GEMM);

    // one-time side streams/events (host objects; not device memory)
    static cudaStream_t s1 = nullptr, s2 = nullptr;
    static cudaEvent_t ev_root = nullptr, ev_wq = nullptr, ev_wk = nullptr,
                       ev_wv = nullptr, ev_wo = nullptr, ev_qk = nullptr,
                       ev_rope = nullptr;
    if (!s1) {
        cudaStreamCreateWithFlags(&s1, cudaStreamNonBlocking);
        cudaStreamCreateWithFlags(&s2, cudaStreamNonBlocking);
        cudaEventCreateWithFlags(&ev_root, cudaEventDisableTiming);
        cudaEventCreateWithFlags(&ev_wq,   cudaEventDisableTiming);
        cudaEventCreateWithFlags(&ev_wk,   cudaEventDisableTiming);
        cudaEventCreateWithFlags(&ev_wv,   cudaEventDisableTiming);
        cudaEventCreateWithFlags(&ev_wo,   cudaEventDisableTiming);
        cudaEventCreateWithFlags(&ev_qk,   cudaEventDisableTiming);
        cudaEventCreateWithFlags(&ev_rope, cudaEventDisableTiming);
    }

    const size_t WSZ = (size_t)GN * GK;
    const int n4x = GM * GK / 4;
    const int n4w = GN * GK / 4;
    dim3 gg(GN / 128, GM / 128);  // (16, 32)

    // fork: root event on main (capture) stream
    cudaEventRecord(ev_root, 0);
    cudaStreamWaitEvent(s1, ev_root, 0);

    // s1: weight cvts, overlapping x-cvt and early GEMMs on main stream
    cvt_split_kernel<<<(n4w + 255) / 256, 256, 0, s1>>>(Wq, wh + 0 * WSZ, wl + 0 * WSZ, n4w);
    cudaEventRecord(ev_wq, s1);
    cvt_split_kernel<<<(n4w + 255) / 256, 256, 0, s1>>>(Wk, wh + 1 * WSZ, wl + 1 * WSZ, n4w);
    cudaEventRecord(ev_wk, s1);
    cvt_split_kernel<<<(n4w + 255) / 256, 256, 0, s1>>>(Wv, wh + 2 * WSZ, wl + 2 * WSZ, n4w);
    cudaEventRecord(ev_wv, s1);
    cvt_split_kernel<<<(n4w + 255) / 256, 256, 0, s1>>>(Wo, wh + 3 * WSZ, wl + 3 * WSZ, n4w);
    cudaEventRecord(ev_wo, s1);

    // main: x cvt, then projection GEMMs (each gated on its weight cvt)
    cvt_split_kernel<<<(n4x + 255) / 256, 256>>>(x, xh, xl, n4x);
    cudaStreamWaitEvent(0, ev_wq, 0);
    gemm_mma_kernel<1><<<gg, 256, SMEM_GEMM>>>(xh, xl, wh + 0 * WSZ, wl + 0 * WSZ,
                                               qp, nullptr, nullptr);
    cudaStreamWaitEvent(0, ev_wk, 0);
    gemm_mma_kernel<1><<<gg, 256, SMEM_GEMM>>>(xh, xl, wh + 1 * WSZ, wl + 1 * WSZ,
                                               kp, nullptr, nullptr);
    cudaEventRecord(ev_qk, 0);

    // s2: rope (mem-bound) overlaps V-GEMM (tensor-bound) on main
    cudaStreamWaitEvent(s2, ev_qk, 0);
    rope_split_kernel<<<(CB * CNH * CT * 64) / 256, 256, 0, s2>>>(cosb, sinb);
    cudaEventRecord(ev_rope, s2);

    cudaStreamWaitEvent(0, ev_wv, 0);
    gemm_mma_kernel<2><<<gg, 256, SMEM_GEMM>>>(xh, xl, wh + 2 * WSZ, wl + 2 * WSZ,
                                               nullptr, vh, vl);

    // join rope, run attention, then output projection (gated on Wo cvt)
    cudaStreamWaitEvent(0, ev_rope, 0);
    attn_mma_kernel<<<dim3(CT / 128, CNH, CB), 256, SMEM_ATTN>>>();

    cudaStreamWaitEvent(0, ev_wo, 0);
    gemm_mma_kernel<0><<<gg, 256, SMEM_GEMM>>>(aoh, aol, wh + 3 * WSZ, wl + 3 * WSZ,
                                               out, nullptr, nullptr);
}

// round 11
// speedup vs baseline: 2.8787x; 1.0640x over previous
#include <cuda_runtime.h>
#include <cuda_bf16.h>
#include <cstdint>
#include <math.h>

// Problem constants
constexpr int CB  = 2;     // batch
constexpr int CT  = 2048;  // seq len
constexpr int CH  = 2048;  // hidden
constexpr int CNH = 16;    // heads
constexpr int CHD = 128;   // head dim
constexpr int GM  = CB * CT;   // 4096
constexpr int GK  = CH;        // 2048
constexpr int GN  = CH;        // 2048

// ---------------------------------------------------------------------------
// Scratch (allocation-free: __device__ globals)
// ---------------------------------------------------------------------------
__device__ float g_q [(size_t)CB * CNH * CT * CHD];  // fp32 Q pre-RoPE [B,NH,T,HD]
__device__ float g_k [(size_t)CB * CNH * CT * CHD];

// split-bf16 planes
__device__ __align__(16) __nv_bfloat16 g_xh [(size_t)GM * GK];
__device__ __align__(16) __nv_bfloat16 g_xl [(size_t)GM * GK];
__device__ __align__(16) __nv_bfloat16 g_wh [4][(size_t)GN * GK];  // q,k,v,o (contiguous)
__device__ __align__(16) __nv_bfloat16 g_wl [4][(size_t)GN * GK];
__device__ __align__(16) __nv_bfloat16 g_qh [(size_t)CB * CNH * CT * CHD];  // scaled
__device__ __align__(16) __nv_bfloat16 g_ql [(size_t)CB * CNH * CT * CHD];
__device__ __align__(16) __nv_bfloat16 g_kh [(size_t)CB * CNH * CT * CHD];
__device__ __align__(16) __nv_bfloat16 g_kl [(size_t)CB * CNH * CT * CHD];
__device__ __align__(16) __nv_bfloat16 g_vh [(size_t)CB * CNH * CT * CHD];
__device__ __align__(16) __nv_bfloat16 g_vl [(size_t)CB * CNH * CT * CHD];
__device__ __align__(16) __nv_bfloat16 g_aoh[(size_t)GM * GK];  // attn out [B*T][H]
__device__ __align__(16) __nv_bfloat16 g_aol[(size_t)GM * GK];

// ---------------------------------------------------------------------------
// Baseline-ISA helpers (all valid on compute_103 virtual arch)
// ---------------------------------------------------------------------------
__device__ __forceinline__ uint32_t smem_to_u32(const void* p) {
    uint32_t a;
    asm("{ .reg .u64 t; cvta.to.shared.u64 t, %1; cvt.u32.u64 %0, t; }"
        : "=r"(a) : "l"(p));
    return a;
}
__device__ __forceinline__ void ldmx4(uint32_t* r, uint32_t addr) {
    asm volatile("ldmatrix.sync.aligned.m8n8.x4.shared.b16 {%0,%1,%2,%3}, [%4];"
        : "=r"(r[0]), "=r"(r[1]), "=r"(r[2]), "=r"(r[3]) : "r"(addr));
}
__device__ __forceinline__ void ldmx4t(uint32_t* r, uint32_t addr) {
    asm volatile("ldmatrix.sync.aligned.m8n8.x4.trans.shared.b16 {%0,%1,%2,%3}, [%4];"
        : "=r"(r[0]), "=r"(r[1]), "=r"(r[2]), "=r"(r[3]) : "r"(addr));
}
__device__ __forceinline__ void mma16816(float* d, const uint32_t* a,
                                         const uint32_t* b) {
    asm volatile(
        "mma.sync.aligned.m16n8k16.row.col.f32.bf16.bf16.f32 "
        "{%0,%1,%2,%3}, {%4,%5,%6,%7}, {%8,%9}, {%0,%1,%2,%3};"
        : "+f"(d[0]), "+f"(d[1]), "+f"(d[2]), "+f"(d[3])
        : "r"(a[0]), "r"(a[1]), "r"(a[2]), "r"(a[3]), "r"(b[0]), "r"(b[1]));
}
__device__ __forceinline__ void cp_async16(uint32_t dst, const void* src) {
    asm volatile("cp.async.cg.shared.global [%0], [%1], 16;"
        :: "r"(dst), "l"(src));
}
#define CP_COMMIT() asm volatile("cp.async.commit_group;" ::: "memory")
#define CP_WAIT0()  asm volatile("cp.async.wait_group 0;" ::: "memory")

__device__ __forceinline__ uint32_t pack_bf16(float a, float b) {
    __nv_bfloat162 h = __float22bfloat162_rn(make_float2(a, b));
    return *(uint32_t*)&h;
}

// ---------------------------------------------------------------------------
// Split conversion: hi = bf16(x), lo = bf16(x - hi)
// ---------------------------------------------------------------------------
__global__ void cvt_split_kernel(const float* __restrict__ src,
                                 __nv_bfloat16* __restrict__ hi,
                                 __nv_bfloat16* __restrict__ lo, int n4)
{
    int i = blockIdx.x * blockDim.x + threadIdx.x;
    if (i >= n4) return;
    float4 v = ((const float4*)src)[i];
    __nv_bfloat16 h[4], l[4];
    h[0] = __float2bfloat16(v.x); l[0] = __float2bfloat16(v.x - __bfloat162float(h[0]));
    h[1] = __float2bfloat16(v.y); l[1] = __float2bfloat16(v.y - __bfloat162float(h[1]));
    h[2] = __float2bfloat16(v.z); l[2] = __float2bfloat16(v.z - __bfloat162float(h[2]));
    h[3] = __float2bfloat16(v.w); l[3] = __float2bfloat16(v.w - __bfloat162float(h[3]));
    *(uint2*)(hi + (size_t)i * 4) = *(uint2*)h;
    *(uint2*)(lo + (size_t)i * 4) = *(uint2*)l;
}

// ---------------------------------------------------------------------------
// GEMM Y = A @ B^T, split-bf16 3-pass, cp.async 2-stage, 2 CTAs/SM.
// MODE 0: fp32 row-major [GM][GN]   (Wo projection -> out)
// MODE 3: fused QKV (N = 3*GN): bn>>11 selects Q(fp32 perm) / K(fp32 perm,
//         via Y2) / V(split-bf16 perm via Yh/Yl).
// ---------------------------------------------------------------------------
constexpr int BKG = 32;
constexpr int ROWB = 80;                         // 64B data + 16 pad
constexpr int TILE_BYTES  = 128 * ROWB;          // 10240
constexpr int STAGE_BYTES = 4 * TILE_BYTES;      // Ah, Al, Bh, Bl
constexpr int SMEM_GEMM   = 2 * STAGE_BYTES;     // 81920 -> 2 CTAs/SM
constexpr int NKB = GK / BKG;                    // 64

template <int MODE>
__global__ __launch_bounds__(256, 2) void gemm_mma_kernel(
    const __nv_bfloat16* __restrict__ Ah, const __nv_bfloat16* __restrict__ Al,
    const __nv_bfloat16* __restrict__ Bh, const __nv_bfloat16* __restrict__ Bl,
    float* __restrict__ Y, float* __restrict__ Y2,
    __nv_bfloat16* __restrict__ Yh, __nv_bfloat16* __restrict__ Yl)
{
    extern __shared__ char sm[];
    const uint32_t sb = smem_to_u32(sm);
    const int tid = threadIdx.x;
    const int wid = tid >> 5, lid = tid & 31;
    const int wm = wid & 1, wn = wid >> 1;
    const int bn = blockIdx.x * 128, bm = blockIdx.y * 128;
    const int lg = lid >> 3, li = lid & 7;

    float acc[4][4][4];
#pragma unroll
    for (int mt = 0; mt < 4; mt++)
#pragma unroll
        for (int nt = 0; nt < 4; nt++)
#pragma unroll
            for (int r = 0; r < 4; r++) acc[mt][nt][r] = 0.f;

    auto issue_stage = [&](int s, int kb) {
#pragma unroll
        for (int i = 0; i < 8; i++) {
            int f = tid + i * 256;
            int pl = f >> 9, rem = f & 511, row = rem >> 2, c = rem & 3;
            const __nv_bfloat16* sp = (pl == 0) ? Ah : (pl == 1) ? Al
                                     : (pl == 2) ? Bh : Bl;
            int rbase = (pl >= 2) ? bn : bm;
            cp_async16(sb + s * STAGE_BYTES + pl * TILE_BYTES + row * ROWB + c * 16,
                       sp + (size_t)(rbase + row) * GK + kb * BKG + c * 8);
        }
    };

    issue_stage(0, 0); CP_COMMIT();

    for (int kb = 0; kb < NKB; kb++) {
        CP_WAIT0();
        __syncthreads();                  // stage kb ready; prev compute done
        if (kb + 1 < NKB) { issue_stage((kb + 1) & 1, kb + 1); CP_COMMIT(); }

        const uint32_t st = sb + (kb & 1) * STAGE_BYTES;
        const uint32_t sAh = st, sAl = st + TILE_BYTES;
        const uint32_t sBh = st + 2 * TILE_BYTES, sBl = st + 3 * TILE_BYTES;

#pragma unroll
        for (int ks = 0; ks < 2; ks++) {
            const int ko = ks * 32;
            const int aoff = ((lg & 1) * 8 + li) * ROWB + ko + (lg >> 1) * 16;
            const int boff = ((lg >> 1) * 8 + li) * ROWB + ko + (lg & 1) * 16;

            uint32_t ah[4][4], bh[4][2];
#pragma unroll
            for (int mt = 0; mt < 4; mt++)
                ldmx4(ah[mt], sAh + (wm * 64 + mt * 16) * ROWB + aoff);
#pragma unroll
            for (int p = 0; p < 2; p++) {
                uint32_t r[4];
                ldmx4(r, sBh + (wn * 32 + p * 16) * ROWB + boff);
                bh[2*p][0] = r[0]; bh[2*p][1] = r[1];
                bh[2*p+1][0] = r[2]; bh[2*p+1][1] = r[3];
            }
            // pass 1: Ah x Bh
#pragma unroll
            for (int mt = 0; mt < 4; mt++)
#pragma unroll
                for (int nt = 0; nt < 4; nt++)
                    mma16816(acc[mt][nt], ah[mt], bh[nt]);
            // pass 2: Al x Bh
            {
                uint32_t al[4][4];
#pragma unroll
                for (int mt = 0; mt < 4; mt++)
                    ldmx4(al[mt], sAl + (wm * 64 + mt * 16) * ROWB + aoff);
#pragma unroll
                for (int mt = 0; mt < 4; mt++)
#pragma unroll
                    for (int nt = 0; nt < 4; nt++)
                        mma16816(acc[mt][nt], al[mt], bh[nt]);
            }
            // pass 3: Ah x Bl
            {
                uint32_t bl[4][2];
#pragma unroll
                for (int p = 0; p < 2; p++) {
                    uint32_t r[4];
                    ldmx4(r, sBl + (wn * 32 + p * 16) * ROWB + boff);
                    bl[2*p][0] = r[0]; bl[2*p][1] = r[1];
                    bl[2*p+1][0] = r[2]; bl[2*p+1][1] = r[3];
                }
#pragma unroll
                for (int mt = 0; mt < 4; mt++)
#pragma unroll
                    for (int nt = 0; nt < 4; nt++)
                        mma16816(acc[mt][nt], ah[mt], bl[nt]);
            }
        }
    }

    const int er = lid >> 2;
    const int ec = (lid & 3) * 2;
#pragma unroll
    for (int mt = 0; mt < 4; mt++) {
#pragma unroll
        for (int half = 0; half < 2; half++) {
            int row = bm + wm * 64 + mt * 16 + half * 8 + er;
            if (MODE == 0) {
                size_t base = (size_t)row * GN + bn;
#pragma unroll
                for (int nt = 0; nt < 4; nt++) {
                    int nc = wn * 32 + nt * 8 + ec;
                    *(float2*)(Y + base + nc) =
                        make_float2(acc[mt][nt][half * 2 + 0],
                                    acc[mt][nt][half * 2 + 1]);
                }
            } else {  // MODE 3: fused QKV
                int b = row >> 11;
                int t = row & (CT - 1);
                int proj = bn >> 11;            // 0=Q, 1=K, 2=V
                int cn   = bn & (GN - 1);       // column within projection
                int head = cn >> 7;
                size_t base = (((size_t)b * CNH + head) * CT + t) * CHD;
#pragma unroll
                for (int nt = 0; nt < 4; nt++) {
                    int nc = wn * 32 + nt * 8 + ec;
                    float v0 = acc[mt][nt][half * 2 + 0];
                    float v1 = acc[mt][nt][half * 2 + 1];
                    if (proj == 2) {
                        __nv_bfloat162 h2 = __float22bfloat162_rn(make_float2(v0, v1));
                        *(uint32_t*)(Yh + base + nc) = *(uint32_t*)&h2;
                        *(uint32_t*)(Yl + base + nc) =
                            pack_bf16(v0 - __bfloat162float(h2.x),
                                      v1 - __bfloat162float(h2.y));
                    } else {
                        float* dst = (proj == 0) ? Y : Y2;
                        *(float2*)(dst + base + nc) = make_float2(v0, v1);
                    }
                }
            }
        }
    }
}

// ---------------------------------------------------------------------------
// RoPE + split: reads fp32 g_q/g_k, writes split bf16 (Q pre-scaled).
// ---------------------------------------------------------------------------
__global__ void rope_split_kernel(const float* __restrict__ cosb,
                                  const float* __restrict__ sinb)
{
    const float scale = 0.08838834764831843f;  // 1/sqrt(128)
    int idx = blockIdx.x * blockDim.x + threadIdx.x;   // < B*NH*T*64
    int d  = idx & 63;
    int t  = (idx >> 6) & (CT - 1);
    int bh = idx >> 17;
    size_t base = ((size_t)bh * CT + t) * CHD;
    float c0 = cosb[t * CHD + d],      c1 = cosb[t * CHD + d + 64];
    float s0 = sinb[t * CHD + d],      s1 = sinb[t * CHD + d + 64];
    float q0 = g_q[base + d], q1 = g_q[base + d + 64];
    float qa = fmaf(q0, c0, -q1 * s0) * scale;
    float qb = fmaf(q1, c1,  q0 * s1) * scale;
    float k0 = g_k[base + d], k1 = g_k[base + d + 64];
    float ka = fmaf(k0, c0, -k1 * s0);
    float kb = fmaf(k1, c1,  k0 * s1);
    __nv_bfloat16 h;
    h = __float2bfloat16(qa); g_qh[base + d] = h;
    g_ql[base + d] = __float2bfloat16(qa - __bfloat162float(h));
    h = __float2bfloat16(qb); g_qh[base + d + 64] = h;
    g_ql[base + d + 64] = __float2bfloat16(qb - __bfloat162float(h));
    h = __float2bfloat16(ka); g_kh[base + d] = h;
    g_kl[base + d] = __float2bfloat16(ka - __bfloat162float(h));
    h = __float2bfloat16(kb); g_kh[base + d + 64] = h;
    g_kl[base + d + 64] = __float2bfloat16(kb - __bfloat162float(h));
}

// ---------------------------------------------------------------------------
// Tensor-core flash attention (causal). qt reversed (heavy first).
// wait -> ONE sync -> issue next -> compute (single barrier per stage).
// ---------------------------------------------------------------------------
constexpr int KROWB    = 272;                    // 256B data + 16 pad
constexpr int KV_PLANE = 64 * KROWB;             // 17408
constexpr int KV_STAGE = 4 * KV_PLANE;           // kh,kl,vh,vl
constexpr int SMEM_ATTN = 2 * KV_STAGE;          // 139264

__global__ __launch_bounds__(256) void attn_mma_kernel()
{
    extern __shared__ char sm[];
    const uint32_t sb = smem_to_u32(sm);
    const int qt = gridDim.x - 1 - blockIdx.x;   // heavy first
    const int h = blockIdx.y, b = blockIdx.z;
    const int tid = threadIdx.x, w = tid >> 5, l = tid & 31;
    const size_t bh = ((size_t)b * CNH + h) * CT * CHD;
    const int fr = l >> 2, t2 = (l & 3) * 2;
    const int lg = l >> 3, li = l & 7;

    const __nv_bfloat16* qhp = g_qh + bh + (size_t)(qt * 128 + w * 16) * CHD;
    const __nv_bfloat16* qlp = g_ql + bh + (size_t)(qt * 128 + w * 16) * CHD;
    uint32_t qhf[8][4];
#pragma unroll
    for (int ks = 0; ks < 8; ks++) {
        int c = ks * 16 + t2;
        qhf[ks][0] = *(const uint32_t*)(qhp + fr * 128 + c);
        qhf[ks][1] = *(const uint32_t*)(qhp + (fr + 8) * 128 + c);
        qhf[ks][2] = *(const uint32_t*)(qhp + fr * 128 + c + 8);
        qhf[ks][3] = *(const uint32_t*)(qhp + (fr + 8) * 128 + c + 8);
    }

    float o[16][4];
#pragma unroll
    for (int nt = 0; nt < 16; nt++)
#pragma unroll
        for (int e = 0; e < 4; e++) o[nt][e] = 0.f;
    float mx[2] = {-1e30f, -1e30f}, ls[2] = {0.f, 0.f};

    const int last = 2 * qt + 1;

    auto issue = [&](int s, int kt) {
        const __nv_bfloat16* srcs[4] = {
            g_kh + bh + (size_t)kt * 64 * CHD, g_kl + bh + (size_t)kt * 64 * CHD,
            g_vh + bh + (size_t)kt * 64 * CHD, g_vl + bh + (size_t)kt * 64 * CHD};
#pragma unroll
        for (int i = 0; i < 16; i++) {
            int f = tid + i * 256;
            int pl = f >> 10, rem = f & 1023, row = rem >> 4, c = rem & 15;
            cp_async16(sb + s * KV_STAGE + pl * KV_PLANE + row * KROWB + c * 16,
                       srcs[pl] + row * 128 + c * 8);
        }
    };

    issue(0, 0); CP_COMMIT();

    for (int kt = 0; kt <= last; kt++) {
        CP_WAIT0();
        __syncthreads();           // stage kt visible; all warps done with kt-1
        if (kt < last) { issue((kt + 1) & 1, kt + 1); CP_COMMIT(); }

        const uint32_t st = sb + (kt & 1) * KV_STAGE;
        const uint32_t kh_s = st, kl_s = st + KV_PLANE;
        const uint32_t vh_s = st + 2 * KV_PLANE, vl_s = st + 3 * KV_PLANE;

        // ---- S = Qs @ K^T (3 passes) ----
        float s4[8][4];
#pragma unroll
        for (int nt = 0; nt < 8; nt++)
#pragma unroll
            for (int e = 0; e < 4; e++) s4[nt][e] = 0.f;

        const int boffb = ((lg >> 1) * 8 + li) * KROWB + (lg & 1) * 16;
#pragma unroll
        for (int ks = 0; ks < 8; ks++) {
            uint32_t bf[8][2];
#pragma unroll
            for (int p = 0; p < 4; p++) {
                uint32_t r[4];
                ldmx4(r, kh_s + p * 16 * KROWB + ks * 32 + boffb);
                bf[2*p][0] = r[0]; bf[2*p][1] = r[1];
                bf[2*p+1][0] = r[2]; bf[2*p+1][1] = r[3];
            }
#pragma unroll
            for (int nt = 0; nt < 8; nt++) mma16816(s4[nt], qhf[ks], bf[nt]);
            uint32_t qlf[4];
            int c = ks * 16 + t2;
            qlf[0] = *(const uint32_t*)(qlp + fr * 128 + c);
            qlf[1] = *(const uint32_t*)(qlp + (fr + 8) * 128 + c);
            qlf[2] = *(const uint32_t*)(qlp + fr * 128 + c + 8);
            qlf[3] = *(const uint32_t*)(qlp + (fr + 8) * 128 + c + 8);
#pragma unroll
            for (int nt = 0; nt < 8; nt++) mma16816(s4[nt], qlf, bf[nt]);
        }
#pragma unroll
        for (int ks = 0; ks < 8; ks++) {
            uint32_t bf[8][2];
#pragma unroll
            for (int p = 0; p < 4; p++) {
                uint32_t r[4];
                ldmx4(r, kl_s + p * 16 * KROWB + ks * 32 + boffb);
                bf[2*p][0] = r[0]; bf[2*p][1] = r[1];
                bf[2*p+1][0] = r[2]; bf[2*p+1][1] = r[3];
            }
#pragma unroll
            for (int nt = 0; nt < 8; nt++) mma16816(s4[nt], qhf[ks], bf[nt]);
        }

        // ---- causal mask ----
        if (kt >= 2 * qt) {
            int row0 = qt * 128 + w * 16 + fr;
#pragma unroll
            for (int nt = 0; nt < 8; nt++) {
                int col0 = kt * 64 + nt * 8 + t2;
#pragma unroll
                for (int e = 0; e < 4; e++) {
                    int row = row0 + 8 * (e >> 1);
                    int col = col0 + (e & 1);
                    if (col > row) s4[nt][e] = -1e30f;
                }
            }
        }

        // ---- online softmax ----
#pragma unroll
        for (int half = 0; half < 2; half++) {
            float rm = -1e30f;
#pragma unroll
            for (int nt = 0; nt < 8; nt++)
                rm = fmaxf(rm, fmaxf(s4[nt][2*half], s4[nt][2*half+1]));
            rm = fmaxf(rm, __shfl_xor_sync(0xffffffffu, rm, 1));
            rm = fmaxf(rm, __shfl_xor_sync(0xffffffffu, rm, 2));
            float mn = fmaxf(mx[half], rm);
            float al = __expf(mx[half] - mn);
            mx[half] = mn;
            float rs = 0.f;
#pragma unroll
            for (int nt = 0; nt < 8; nt++) {
                s4[nt][2*half]   = __expf(s4[nt][2*half]   - mn);
                s4[nt][2*half+1] = __expf(s4[nt][2*half+1] - mn);
                rs += s4[nt][2*half] + s4[nt][2*half+1];
            }
            rs += __shfl_xor_sync(0xffffffffu, rs, 1);
            rs += __shfl_xor_sync(0xffffffffu, rs, 2);
            ls[half] = ls[half] * al + rs;
#pragma unroll
            for (int nt = 0; nt < 16; nt++) {
                o[nt][2*half]   *= al;
                o[nt][2*half+1] *= al;
            }
        }

        // ---- P fragments (hi/lo) ----
        uint32_t pha[4][4], pla[4][4];
#pragma unroll
        for (int kc = 0; kc < 4; kc++) {
#pragma unroll
            for (int j = 0; j < 4; j++) {
                int nt = 2 * kc + (j >> 1);
                int eb = (j & 1) * 2;
                float x0 = s4[nt][eb], x1 = s4[nt][eb + 1];
                __nv_bfloat162 h2 = __float22bfloat162_rn(make_float2(x0, x1));
                pha[kc][j] = *(uint32_t*)&h2;
                pla[kc][j] = pack_bf16(x0 - __bfloat162float(h2.x),
                                       x1 - __bfloat162float(h2.y));
            }
        }

        // ---- O += P @ V (3 passes) ----
#pragma unroll
        for (int kc = 0; kc < 4; kc++) {
            uint32_t vb[16][2];
#pragma unroll
            for (int p = 0; p < 8; p++) {
                uint32_t r[4];
                uint32_t addr = vh_s + (kc * 16 + (lg & 1) * 8 + li) * KROWB
                                + (p * 16 + (lg >> 1) * 8) * 2;
                ldmx4t(r, addr);
                vb[2*p][0] = r[0]; vb[2*p][1] = r[1];
                vb[2*p+1][0] = r[2]; vb[2*p+1][1] = r[3];
            }
#pragma unroll
            for (int nt = 0; nt < 16; nt++) mma16816(o[nt], pha[kc], vb[nt]);
#pragma unroll
            for (int nt = 0; nt < 16; nt++) mma16816(o[nt], pla[kc], vb[nt]);
#pragma unroll
            for (int p = 0; p < 8; p++) {
                uint32_t r[4];
                uint32_t addr = vl_s + (kc * 16 + (lg & 1) * 8 + li) * KROWB
                                + (p * 16 + (lg >> 1) * 8) * 2;
                ldmx4t(r, addr);
                vb[2*p][0] = r[0]; vb[2*p][1] = r[1];
                vb[2*p+1][0] = r[2]; vb[2*p+1][1] = r[3];
            }
#pragma unroll
            for (int nt = 0; nt < 16; nt++) mma16816(o[nt], pha[kc], vb[nt]);
        }
    }

    // ---- epilogue ----
    float inv0 = 1.f / ls[0], inv1 = 1.f / ls[1];
    int row0 = qt * 128 + w * 16 + fr;
    size_t r0 = ((size_t)b * CT + row0) * CH + h * CHD;
    size_t r1 = ((size_t)b * CT + row0 + 8) * CH + h * CHD;
#pragma unroll
    for (int nt = 0; nt < 16; nt++) {
        int col = nt * 8 + t2;
        float v0 = o[nt][0] * inv0, v1 = o[nt][1] * inv0;
        __nv_bfloat162 h2 = __float22bfloat162_rn(make_float2(v0, v1));
        *(uint32_t*)(g_aoh + r0 + col) = *(uint32_t*)&h2;
        *(uint32_t*)(g_aol + r0 + col) =
            pack_bf16(v0 - __bfloat162float(h2.x), v1 - __bfloat162float(h2.y));
        float v2 = o[nt][2] * inv1, v3 = o[nt][3] * inv1;
        __nv_bfloat162 h3 = __float22bfloat162_rn(make_float2(v2, v3));
        *(uint32_t*)(g_aoh + r1 + col) = *(uint32_t*)&h3;
        *(uint32_t*)(g_aol + r1 + col) =
            pack_bf16(v2 - __bfloat162float(h3.x), v3 - __bfloat162float(h3.y));
    }
}

// ---------------------------------------------------------------------------
// Launch — fused QKV GEMM (one 1536-CTA launch instead of 3x512) + side
// streams for weight cvts. Streams/events created lazily once.
// ---------------------------------------------------------------------------
extern "C" void kernel_launch(void* const* d_in, const int* in_sizes, int n_in,
                              void* d_out, int out_size)
{
    (void)in_sizes; (void)n_in; (void)out_size;
    const float* x    = (const float*)d_in[0];
    const float* cosb = (const float*)d_in[1];
    const float* sinb = (const float*)d_in[2];
    const float* Wq   = (const float*)d_in[3];
    const float* Wk   = (const float*)d_in[4];
    const float* Wv   = (const float*)d_in[5];
    const float* Wo   = (const float*)d_in[6];
    float* out = (float*)d_out;

    float *qp, *kp;
    cudaGetSymbolAddress((void**)&qp, g_q);
    cudaGetSymbolAddress((void**)&kp, g_k);
    __nv_bfloat16 *xh, *xl, *wh, *wl, *vh, *vl, *aoh, *aol;
    cudaGetSymbolAddress((void**)&xh,  g_xh);
    cudaGetSymbolAddress((void**)&xl,  g_xl);
    cudaGetSymbolAddress((void**)&wh,  g_wh);
    cudaGetSymbolAddress((void**)&wl,  g_wl);
    cudaGetSymbolAddress((void**)&vh,  g_vh);
    cudaGetSymbolAddress((void**)&vl,  g_vl);
    cudaGetSymbolAddress((void**)&aoh, g_aoh);
    cudaGetSymbolAddress((void**)&aol, g_aol);

    cudaFuncSetAttribute(attn_mma_kernel,
                         cudaFuncAttributeMaxDynamicSharedMemorySize, SMEM_ATTN);
    cudaFuncSetAttribute(gemm_mma_kernel<0>,
                         cudaFuncAttributeMaxDynamicSharedMemorySize, SMEM_GEMM);
    cudaFuncSetAttribute(gemm_mma_kernel<3>,
                         cudaFuncAttributeMaxDynamicSharedMemorySize, SMEM_GEMM);

    static cudaStream_t s1 = nullptr;
    static cudaEvent_t ev_root = nullptr, ev_wv = nullptr, ev_wo = nullptr;
    if (!s1) {
        cudaStreamCreateWithFlags(&s1, cudaStreamNonBlocking);
        cudaEventCreateWithFlags(&ev_root, cudaEventDisableTiming);
        cudaEventCreateWithFlags(&ev_wv,   cudaEventDisableTiming);
        cudaEventCreateWithFlags(&ev_wo,   cudaEventDisableTiming);
    }

    const size_t WSZ = (size_t)GN * GK;
    const int n4x = GM * GK / 4;
    const int n4w = GN * GK / 4;

    // fork: weight cvts on s1 overlap x cvt on main
    cudaEventRecord(ev_root, 0);
    cudaStreamWaitEvent(s1, ev_root, 0);
    cvt_split_kernel<<<(n4w + 255) / 256, 256, 0, s1>>>(Wq, wh + 0 * WSZ, wl + 0 * WSZ, n4w);
    cvt_split_kernel<<<(n4w + 255) / 256, 256, 0, s1>>>(Wk, wh + 1 * WSZ, wl + 1 * WSZ, n4w);
    cvt_split_kernel<<<(n4w + 255) / 256, 256, 0, s1>>>(Wv, wh + 2 * WSZ, wl + 2 * WSZ, n4w);
    cudaEventRecord(ev_wv, s1);   // Q,K,V weight planes ready
    cvt_split_kernel<<<(n4w + 255) / 256, 256, 0, s1>>>(Wo, wh + 3 * WSZ, wl + 3 * WSZ, n4w);
    cudaEventRecord(ev_wo, s1);

    // main: x cvt, then ONE fused QKV GEMM (N = 6144)
    cvt_split_kernel<<<(n4x + 255) / 256, 256>>>(x, xh, xl, n4x);
    cudaStreamWaitEvent(0, ev_wv, 0);
    gemm_mma_kernel<3><<<dim3(3 * GN / 128, GM / 128), 256, SMEM_GEMM>>>(
        xh, xl, wh, wl, qp, kp, vh, vl);

    rope_split_kernel<<<(CB * CNH * CT * 64) / 256, 256>>>(cosb, sinb);
    attn_mma_kernel<<<dim3(CT / 128, CNH, CB), 256, SMEM_ATTN>>>();

    cudaStreamWaitEvent(0, ev_wo, 0);
    gemm_mma_kernel<0><<<dim3(GN / 128, GM / 128), 256, SMEM_GEMM>>>(
        aoh, aol, wh + 3 * WSZ, wl + 3 * WSZ, out, nullptr, nullptr, nullptr);
}

// round 12
// speedup vs baseline: 2.8935x; 1.0051x over previous
#include <cuda_runtime.h>
#include <cuda_bf16.h>
#include <cstdint>
#include <math.h>

// Problem constants
constexpr int CB  = 2;     // batch
constexpr int CT  = 2048;  // seq len
constexpr int CH  = 2048;  // hidden
constexpr int CNH = 16;    // heads
constexpr int CHD = 128;   // head dim
constexpr int GM  = CB * CT;   // 4096
constexpr int GK  = CH;        // 2048
constexpr int GN  = CH;        // 2048

// ---------------------------------------------------------------------------
// Scratch (allocation-free: __device__ globals)
// ---------------------------------------------------------------------------
__device__ __align__(16) __nv_bfloat16 g_xh [(size_t)GM * GK];
__device__ __align__(16) __nv_bfloat16 g_xl [(size_t)GM * GK];
__device__ __align__(16) __nv_bfloat16 g_wh [4][(size_t)GN * GK];  // q,k,v,o
__device__ __align__(16) __nv_bfloat16 g_wl [4][(size_t)GN * GK];
__device__ __align__(16) __nv_bfloat16 g_qh [(size_t)CB * CNH * CT * CHD];  // scaled
__device__ __align__(16) __nv_bfloat16 g_ql [(size_t)CB * CNH * CT * CHD];
__device__ __align__(16) __nv_bfloat16 g_kh [(size_t)CB * CNH * CT * CHD];
__device__ __align__(16) __nv_bfloat16 g_kl [(size_t)CB * CNH * CT * CHD];
__device__ __align__(16) __nv_bfloat16 g_vh [(size_t)CB * CNH * CT * CHD];
__device__ __align__(16) __nv_bfloat16 g_vl [(size_t)CB * CNH * CT * CHD];
__device__ __align__(16) __nv_bfloat16 g_aoh[(size_t)GM * GK];  // attn out [B*T][H]
__device__ __align__(16) __nv_bfloat16 g_aol[(size_t)GM * GK];

// ---------------------------------------------------------------------------
// Baseline-ISA helpers (all valid on compute_103 virtual arch)
// ---------------------------------------------------------------------------
__device__ __forceinline__ uint32_t smem_to_u32(const void* p) {
    uint32_t a;
    asm("{ .reg .u64 t; cvta.to.shared.u64 t, %1; cvt.u32.u64 %0, t; }"
        : "=r"(a) : "l"(p));
    return a;
}
__device__ __forceinline__ void ldmx4(uint32_t* r, uint32_t addr) {
    asm volatile("ldmatrix.sync.aligned.m8n8.x4.shared.b16 {%0,%1,%2,%3}, [%4];"
        : "=r"(r[0]), "=r"(r[1]), "=r"(r[2]), "=r"(r[3]) : "r"(addr));
}
__device__ __forceinline__ void ldmx4t(uint32_t* r, uint32_t addr) {
    asm volatile("ldmatrix.sync.aligned.m8n8.x4.trans.shared.b16 {%0,%1,%2,%3}, [%4];"
        : "=r"(r[0]), "=r"(r[1]), "=r"(r[2]), "=r"(r[3]) : "r"(addr));
}
__device__ __forceinline__ void mma16816(float* d, const uint32_t* a,
                                         const uint32_t* b) {
    asm volatile(
        "mma.sync.aligned.m16n8k16.row.col.f32.bf16.bf16.f32 "
        "{%0,%1,%2,%3}, {%4,%5,%6,%7}, {%8,%9}, {%0,%1,%2,%3};"
        : "+f"(d[0]), "+f"(d[1]), "+f"(d[2]), "+f"(d[3])
        : "r"(a[0]), "r"(a[1]), "r"(a[2]), "r"(a[3]), "r"(b[0]), "r"(b[1]));
}
__device__ __forceinline__ void cp_async16(uint32_t dst, const void* src) {
    asm volatile("cp.async.cg.shared.global [%0], [%1], 16;"
        :: "r"(dst), "l"(src));
}
#define CP_COMMIT() asm volatile("cp.async.commit_group;" ::: "memory")
#define CP_WAIT0()  asm volatile("cp.async.wait_group 0;" ::: "memory")

__device__ __forceinline__ uint32_t pack_bf16(float a, float b) {
    __nv_bfloat162 h = __float22bfloat162_rn(make_float2(a, b));
    return *(uint32_t*)&h;
}

// ---------------------------------------------------------------------------
// Split conversion: hi = bf16(x), lo = bf16(x - hi)
// ---------------------------------------------------------------------------
__global__ void cvt_split_kernel(const float* __restrict__ src,
                                 __nv_bfloat16* __restrict__ hi,
                                 __nv_bfloat16* __restrict__ lo, int n4)
{
    int i = blockIdx.x * blockDim.x + threadIdx.x;
    if (i >= n4) return;
    float4 v = ((const float4*)src)[i];
    __nv_bfloat16 h[4], l[4];
    h[0] = __float2bfloat16(v.x); l[0] = __float2bfloat16(v.x - __bfloat162float(h[0]));
    h[1] = __float2bfloat16(v.y); l[1] = __float2bfloat16(v.y - __bfloat162float(h[1]));
    h[2] = __float2bfloat16(v.z); l[2] = __float2bfloat16(v.z - __bfloat162float(h[2]));
    h[3] = __float2bfloat16(v.w); l[3] = __float2bfloat16(v.w - __bfloat162float(h[3]));
    *(uint2*)(hi + (size_t)i * 4) = *(uint2*)h;
    *(uint2*)(lo + (size_t)i * 4) = *(uint2*)l;
}

// ---------------------------------------------------------------------------
// GEMM Y = A @ B^T, split-bf16 3-pass, cp.async 2-stage, 2 CTAs/SM.
// MODE 0: fp32 row-major [GM][GN] (Wo -> out), rows offset by bm_off.
// MODE 3: fused QKV (N = 3*GN). Per-CTA proj = bn>>11:
//         Q/K -> acc staged via smem, RoPE applied (Q scaled), split-bf16
//                written directly into g_qh/ql/kh/kl [B,NH,T,HD];
//         V   -> split-bf16 direct into g_vh/vl.
// ---------------------------------------------------------------------------
constexpr int BKG = 32;
constexpr int ROWB = 80;                         // 64B data + 16 pad
constexpr int TILE_BYTES  = 128 * ROWB;          // 10240
constexpr int STAGE_BYTES = 4 * TILE_BYTES;      // Ah, Al, Bh, Bl
constexpr int SMEM_GEMM   = 2 * STAGE_BYTES;     // 81920 -> 2 CTAs/SM
constexpr int NKB = GK / BKG;                    // 64

template <int MODE>
__global__ __launch_bounds__(256, 2) void gemm_mma_kernel(
    const __nv_bfloat16* __restrict__ Ah, const __nv_bfloat16* __restrict__ Al,
    const __nv_bfloat16* __restrict__ Bh, const __nv_bfloat16* __restrict__ Bl,
    float* __restrict__ Y, const float* __restrict__ cosb,
    const float* __restrict__ sinb, int bm_off)
{
    extern __shared__ char sm[];
    const uint32_t sb = smem_to_u32(sm);
    const int tid = threadIdx.x;
    const int wid = tid >> 5, lid = tid & 31;
    const int wm = wid & 1, wn = wid >> 1;
    const int bn = blockIdx.x * 128, bm = blockIdx.y * 128 + bm_off;
    const int lg = lid >> 3, li = lid & 7;

    float acc[4][4][4];
#pragma unroll
    for (int mt = 0; mt < 4; mt++)
#pragma unroll
        for (int nt = 0; nt < 4; nt++)
#pragma unroll
            for (int r = 0; r < 4; r++) acc[mt][nt][r] = 0.f;

    auto issue_stage = [&](int s, int kb) {
#pragma unroll
        for (int i = 0; i < 8; i++) {
            int f = tid + i * 256;
            int pl = f >> 9, rem = f & 511, row = rem >> 2, c = rem & 3;
            const __nv_bfloat16* sp = (pl == 0) ? Ah : (pl == 1) ? Al
                                     : (pl == 2) ? Bh : Bl;
            int rbase = (pl >= 2) ? bn : bm;
            cp_async16(sb + s * STAGE_BYTES + pl * TILE_BYTES + row * ROWB + c * 16,
                       sp + (size_t)(rbase + row) * GK + kb * BKG + c * 8);
        }
    };

    issue_stage(0, 0); CP_COMMIT();

    for (int kb = 0; kb < NKB; kb++) {
        CP_WAIT0();
        __syncthreads();                  // stage kb ready; prev compute done
        if (kb + 1 < NKB) { issue_stage((kb + 1) & 1, kb + 1); CP_COMMIT(); }

        const uint32_t st = sb + (kb & 1) * STAGE_BYTES;
        const uint32_t sAh = st, sAl = st + TILE_BYTES;
        const uint32_t sBh = st + 2 * TILE_BYTES, sBl = st + 3 * TILE_BYTES;

#pragma unroll
        for (int ks = 0; ks < 2; ks++) {
            const int ko = ks * 32;
            const int aoff = ((lg & 1) * 8 + li) * ROWB + ko + (lg >> 1) * 16;
            const int boff = ((lg >> 1) * 8 + li) * ROWB + ko + (lg & 1) * 16;

            uint32_t ah[4][4], bh[4][2];
#pragma unroll
            for (int mt = 0; mt < 4; mt++)
                ldmx4(ah[mt], sAh + (wm * 64 + mt * 16) * ROWB + aoff);
#pragma unroll
            for (int p = 0; p < 2; p++) {
                uint32_t r[4];
                ldmx4(r, sBh + (wn * 32 + p * 16) * ROWB + boff);
                bh[2*p][0] = r[0]; bh[2*p][1] = r[1];
                bh[2*p+1][0] = r[2]; bh[2*p+1][1] = r[3];
            }
            // pass 1: Ah x Bh
#pragma unroll
            for (int mt = 0; mt < 4; mt++)
#pragma unroll
                for (int nt = 0; nt < 4; nt++)
                    mma16816(acc[mt][nt], ah[mt], bh[nt]);
            // pass 2: Al x Bh
            {
                uint32_t al[4][4];
#pragma unroll
                for (int mt = 0; mt < 4; mt++)
                    ldmx4(al[mt], sAl + (wm * 64 + mt * 16) * ROWB + aoff);
#pragma unroll
                for (int mt = 0; mt < 4; mt++)
#pragma unroll
                    for (int nt = 0; nt < 4; nt++)
                        mma16816(acc[mt][nt], al[mt], bh[nt]);
            }
            // pass 3: Ah x Bl
            {
                uint32_t bl[4][2];
#pragma unroll
                for (int p = 0; p < 2; p++) {
                    uint32_t r[4];
                    ldmx4(r, sBl + (wn * 32 + p * 16) * ROWB + boff);
                    bl[2*p][0] = r[0]; bl[2*p][1] = r[1];
                    bl[2*p+1][0] = r[2]; bl[2*p+1][1] = r[3];
                }
#pragma unroll
                for (int mt = 0; mt < 4; mt++)
#pragma unroll
                    for (int nt = 0; nt < 4; nt++)
                        mma16816(acc[mt][nt], ah[mt], bl[nt]);
            }
        }
    }

    const int er = lid >> 2;
    const int ec = (lid & 3) * 2;

    if (MODE == 0) {
#pragma unroll
        for (int mt = 0; mt < 4; mt++)
#pragma unroll
            for (int half = 0; half < 2; half++) {
                int row = bm + wm * 64 + mt * 16 + half * 8 + er;
                size_t base = (size_t)row * GN + bn;
#pragma unroll
                for (int nt = 0; nt < 4; nt++) {
                    int nc = wn * 32 + nt * 8 + ec;
                    *(float2*)(Y + base + nc) =
                        make_float2(acc[mt][nt][half * 2 + 0],
                                    acc[mt][nt][half * 2 + 1]);
                }
            }
    } else {  // MODE 3 fused QKV
        const int proj = bn >> 11;            // 0=Q, 1=K, 2=V (uniform per CTA)
        const int cn   = bn & (GN - 1);
        const int head = cn >> 7;
        if (proj == 2) {
#pragma unroll
            for (int mt = 0; mt < 4; mt++)
#pragma unroll
                for (int half = 0; half < 2; half++) {
                    int row = bm + wm * 64 + mt * 16 + half * 8 + er;
                    int b = row >> 11;
                    int t = row & (CT - 1);
                    size_t base = (((size_t)b * CNH + head) * CT + t) * CHD;
#pragma unroll
                    for (int nt = 0; nt < 4; nt++) {
                        int nc = wn * 32 + nt * 8 + ec;
                        float v0 = acc[mt][nt][half * 2 + 0];
                        float v1 = acc[mt][nt][half * 2 + 1];
                        __nv_bfloat162 h2 = __float22bfloat162_rn(make_float2(v0, v1));
                        *(uint32_t*)(g_vh + base + nc) = *(uint32_t*)&h2;
                        *(uint32_t*)(g_vl + base + nc) =
                            pack_bf16(v0 - __bfloat162float(h2.x),
                                      v1 - __bfloat162float(h2.y));
                    }
                }
        } else {
            // Q/K: stage fp32 tile in smem, apply RoPE, write split-bf16.
            float* smf = (float*)sm;          // [128][132] fp32 (67584 B)
            __syncthreads();                  // mainloop smem reads done
#pragma unroll
            for (int mt = 0; mt < 4; mt++)
#pragma unroll
                for (int half = 0; half < 2; half++) {
                    int rl = wm * 64 + mt * 16 + half * 8 + er;
#pragma unroll
                    for (int nt = 0; nt < 4; nt++) {
                        int cl = wn * 32 + nt * 8 + ec;
                        smf[rl * 132 + cl]     = acc[mt][nt][half * 2 + 0];
                        smf[rl * 132 + cl + 1] = acc[mt][nt][half * 2 + 1];
                    }
                }
            __syncthreads();
            const float scale = (proj == 0) ? 0.08838834764831843f : 1.f;
            __nv_bfloat16* Oh = (proj == 0) ? g_qh : g_kh;
            __nv_bfloat16* Ol = (proj == 0) ? g_ql : g_kl;
#pragma unroll
            for (int i = 0; i < 32; i++) {
                int idx = tid + i * 256;      // 8192 (row, d<64) pairs
                int rl = idx >> 6, d = idx & 63;
                int grow = bm + rl;
                int t = grow & (CT - 1), b = grow >> 11;
                float x0 = smf[rl * 132 + d];
                float x1 = smf[rl * 132 + d + 64];
                float c0 = cosb[t * CHD + d], c1 = cosb[t * CHD + d + 64];
                float s0 = sinb[t * CHD + d], s1 = sinb[t * CHD + d + 64];
                float ya = fmaf(x0, c0, -x1 * s0) * scale;
                float yb = fmaf(x1, c1,  x0 * s1) * scale;
                size_t base = (((size_t)b * CNH + head) * CT + t) * CHD;
                __nv_bfloat16 hh;
                hh = __float2bfloat16(ya);
                Oh[base + d] = hh;
                Ol[base + d] = __float2bfloat16(ya - __bfloat162float(hh));
                hh = __float2bfloat16(yb);
                Oh[base + d + 64] = hh;
                Ol[base + d + 64] = __float2bfloat16(yb - __bfloat162float(hh));
            }
        }
    }
}

// ---------------------------------------------------------------------------
// Tensor-core flash attention (causal). qt reversed (heavy first).
// Batch passed as param so b=0 / b=1 are separate launches (Wo overlap).
// ---------------------------------------------------------------------------
constexpr int KROWB    = 272;                    // 256B data + 16 pad
constexpr int KV_PLANE = 64 * KROWB;             // 17408
constexpr int KV_STAGE = 4 * KV_PLANE;           // kh,kl,vh,vl
constexpr int SMEM_ATTN = 2 * KV_STAGE;          // 139264

__global__ __launch_bounds__(256) void attn_mma_kernel(int bparam)
{
    extern __shared__ char sm[];
    const uint32_t sb = smem_to_u32(sm);
    const int qt = gridDim.x - 1 - blockIdx.x;   // heavy first
    const int h = blockIdx.y, b = bparam;
    const int tid = threadIdx.x, w = tid >> 5, l = tid & 31;
    const size_t bh = ((size_t)b * CNH + h) * CT * CHD;
    const int fr = l >> 2, t2 = (l & 3) * 2;
    const int lg = l >> 3, li = l & 7;

    const __nv_bfloat16* qhp = g_qh + bh + (size_t)(qt * 128 + w * 16) * CHD;
    const __nv_bfloat16* qlp = g_ql + bh + (size_t)(qt * 128 + w * 16) * CHD;
    uint32_t qhf[8][4];
#pragma unroll
    for (int ks = 0; ks < 8; ks++) {
        int c = ks * 16 + t2;
        qhf[ks][0] = *(const uint32_t*)(qhp + fr * 128 + c);
        qhf[ks][1] = *(const uint32_t*)(qhp + (fr + 8) * 128 + c);
        qhf[ks][2] = *(const uint32_t*)(qhp + fr * 128 + c + 8);
        qhf[ks][3] = *(const uint32_t*)(qhp + (fr + 8) * 128 + c + 8);
    }

    float o[16][4];
#pragma unroll
    for (int nt = 0; nt < 16; nt++)
#pragma unroll
        for (int e = 0; e < 4; e++) o[nt][e] = 0.f;
    float mx[2] = {-1e30f, -1e30f}, ls[2] = {0.f, 0.f};

    const int last = 2 * qt + 1;

    auto issue = [&](int s, int kt) {
        const __nv_bfloat16* srcs[4] = {
            g_kh + bh + (size_t)kt * 64 * CHD, g_kl + bh + (size_t)kt * 64 * CHD,
            g_vh + bh + (size_t)kt * 64 * CHD, g_vl + bh + (size_t)kt * 64 * CHD};
#pragma unroll
        for (int i = 0; i < 16; i++) {
            int f = tid + i * 256;
            int pl = f >> 10, rem = f & 1023, row = rem >> 4, c = rem & 15;
            cp_async16(sb + s * KV_STAGE + pl * KV_PLANE + row * KROWB + c * 16,
                       srcs[pl] + row * 128 + c * 8);
        }
    };

    issue(0, 0); CP_COMMIT();

    for (int kt = 0; kt <= last; kt++) {
        CP_WAIT0();
        __syncthreads();           // stage kt visible; all warps done with kt-1
        if (kt < last) { issue((kt + 1) & 1, kt + 1); CP_COMMIT(); }

        const uint32_t st = sb + (kt & 1) * KV_STAGE;
        const uint32_t kh_s = st, kl_s = st + KV_PLANE;
        const uint32_t vh_s = st + 2 * KV_PLANE, vl_s = st + 3 * KV_PLANE;

        // ---- S = Qs @ K^T (3 passes) ----
        float s4[8][4];
#pragma unroll
        for (int nt = 0; nt < 8; nt++)
#pragma unroll
            for (int e = 0; e < 4; e++) s4[nt][e] = 0.f;

        const int boffb = ((lg >> 1) * 8 + li) * KROWB + (lg & 1) * 16;
#pragma unroll
        for (int ks = 0; ks < 8; ks++) {
            uint32_t bf[8][2];
#pragma unroll
            for (int p = 0; p < 4; p++) {
                uint32_t r[4];
                ldmx4(r, kh_s + p * 16 * KROWB + ks * 32 + boffb);
                bf[2*p][0] = r[0]; bf[2*p][1] = r[1];
                bf[2*p+1][0] = r[2]; bf[2*p+1][1] = r[3];
            }
#pragma unroll
            for (int nt = 0; nt < 8; nt++) mma16816(s4[nt], qhf[ks], bf[nt]);
            uint32_t qlf[4];
            int c = ks * 16 + t2;
            qlf[0] = *(const uint32_t*)(qlp + fr * 128 + c);
            qlf[1] = *(const uint32_t*)(qlp + (fr + 8) * 128 + c);
            qlf[2] = *(const uint32_t*)(qlp + fr * 128 + c + 8);
            qlf[3] = *(const uint32_t*)(qlp + (fr + 8) * 128 + c + 8);
#pragma unroll
            for (int nt = 0; nt < 8; nt++) mma16816(s4[nt], qlf, bf[nt]);
        }
#pragma unroll
        for (int ks = 0; ks < 8; ks++) {
            uint32_t bf[8][2];
#pragma unroll
            for (int p = 0; p < 4; p++) {
                uint32_t r[4];
                ldmx4(r, kl_s + p * 16 * KROWB + ks * 32 + boffb);
                bf[2*p][0] = r[0]; bf[2*p][1] = r[1];
                bf[2*p+1][0] = r[2]; bf[2*p+1][1] = r[3];
            }
#pragma unroll
            for (int nt = 0; nt < 8; nt++) mma16816(s4[nt], qhf[ks], bf[nt]);
        }

        // ---- causal mask ----
        if (kt >= 2 * qt) {
            int row0 = qt * 128 + w * 16 + fr;
#pragma unroll
            for (int nt = 0; nt < 8; nt++) {
                int col0 = kt * 64 + nt * 8 + t2;
#pragma unroll
                for (int e = 0; e < 4; e++) {
                    int row = row0 + 8 * (e >> 1);
                    int col = col0 + (e & 1);
                    if (col > row) s4[nt][e] = -1e30f;
                }
            }
        }

        // ---- online softmax ----
#pragma unroll
        for (int half = 0; half < 2; half++) {
            float rm = -1e30f;
#pragma unroll
            for (int nt = 0; nt < 8; nt++)
                rm = fmaxf(rm, fmaxf(s4[nt][2*half], s4[nt][2*half+1]));
            rm = fmaxf(rm, __shfl_xor_sync(0xffffffffu, rm, 1));
            rm = fmaxf(rm, __shfl_xor_sync(0xffffffffu, rm, 2));
            float mn = fmaxf(mx[half], rm);
            float al = __expf(mx[half] - mn);
            mx[half] = mn;
            float rs = 0.f;
#pragma unroll
            for (int nt = 0; nt < 8; nt++) {
                s4[nt][2*half]   = __expf(s4[nt][2*half]   - mn);
                s4[nt][2*half+1] = __expf(s4[nt][2*half+1] - mn);
                rs += s4[nt][2*half] + s4[nt][2*half+1];
            }
            rs += __shfl_xor_sync(0xffffffffu, rs, 1);
            rs += __shfl_xor_sync(0xffffffffu, rs, 2);
            ls[half] = ls[half] * al + rs;
#pragma unroll
            for (int nt = 0; nt < 16; nt++) {
                o[nt][2*half]   *= al;
                o[nt][2*half+1] *= al;
            }
        }

        // ---- P fragments (hi/lo) ----
        uint32_t pha[4][4], pla[4][4];
#pragma unroll
        for (int kc = 0; kc < 4; kc++) {
#pragma unroll
            for (int j = 0; j < 4; j++) {
                int nt = 2 * kc + (j >> 1);
                int eb = (j & 1) * 2;
                float x0 = s4[nt][eb], x1 = s4[nt][eb + 1];
                __nv_bfloat162 h2 = __float22bfloat162_rn(make_float2(x0, x1));
                pha[kc][j] = *(uint32_t*)&h2;
                pla[kc][j] = pack_bf16(x0 - __bfloat162float(h2.x),
                                       x1 - __bfloat162float(h2.y));
            }
        }

        // ---- O += P @ V (3 passes) ----
#pragma unroll
        for (int kc = 0; kc < 4; kc++) {
            uint32_t vb[16][2];
#pragma unroll
            for (int p = 0; p < 8; p++) {
                uint32_t r[4];
                uint32_t addr = vh_s + (kc * 16 + (lg & 1) * 8 + li) * KROWB
                                + (p * 16 + (lg >> 1) * 8) * 2;
                ldmx4t(r, addr);
                vb[2*p][0] = r[0]; vb[2*p][1] = r[1];
                vb[2*p+1][0] = r[2]; vb[2*p+1][1] = r[3];
            }
#pragma unroll
            for (int nt = 0; nt < 16; nt++) mma16816(o[nt], pha[kc], vb[nt]);
#pragma unroll
            for (int nt = 0; nt < 16; nt++) mma16816(o[nt], pla[kc], vb[nt]);
#pragma unroll
            for (int p = 0; p < 8; p++) {
                uint32_t r[4];
                uint32_t addr = vl_s + (kc * 16 + (lg & 1) * 8 + li) * KROWB
                                + (p * 16 + (lg >> 1) * 8) * 2;
                ldmx4t(r, addr);
                vb[2*p][0] = r[0]; vb[2*p][1] = r[1];
                vb[2*p+1][0] = r[2]; vb[2*p+1][1] = r[3];
            }
#pragma unroll
            for (int nt = 0; nt < 16; nt++) mma16816(o[nt], pha[kc], vb[nt]);
        }
    }

    // ---- epilogue ----
    float inv0 = 1.f / ls[0], inv1 = 1.f / ls[1];
    int row0 = qt * 128 + w * 16 + fr;
    size_t r0 = ((size_t)b * CT + row0) * CH + h * CHD;
    size_t r1 = ((size_t)b * CT + row0 + 8) * CH + h * CHD;
#pragma unroll
    for (int nt = 0; nt < 16; nt++) {
        int col = nt * 8 + t2;
        float v0 = o[nt][0] * inv0, v1 = o[nt][1] * inv0;
        __nv_bfloat162 h2 = __float22bfloat162_rn(make_float2(v0, v1));
        *(uint32_t*)(g_aoh + r0 + col) = *(uint32_t*)&h2;
        *(uint32_t*)(g_aol + r0 + col) =
            pack_bf16(v0 - __bfloat162float(h2.x), v1 - __bfloat162float(h2.y));
        float v2 = o[nt][2] * inv1, v3 = o[nt][3] * inv1;
        __nv_bfloat162 h3 = __float22bfloat162_rn(make_float2(v2, v3));
        *(uint32_t*)(g_aoh + r1 + col) = *(uint32_t*)&h3;
        *(uint32_t*)(g_aol + r1 + col) =
            pack_bf16(v2 - __bfloat162float(h3.x), v3 - __bfloat162float(h3.y));
    }
}

// ---------------------------------------------------------------------------
// Launch — QKV GEMM with fused RoPE epilogue; attention split by batch so
// the Wo GEMM for b=0's rows overlaps attention for b=1.
// ---------------------------------------------------------------------------
extern "C" void kernel_launch(void* const* d_in, const int* in_sizes, int n_in,
                              void* d_out, int out_size)
{
    (void)in_sizes; (void)n_in; (void)out_size;
    const float* x    = (const float*)d_in[0];
    const float* cosb = (const float*)d_in[1];
    const float* sinb = (const float*)d_in[2];
    const float* Wq   = (const float*)d_in[3];
    const float* Wk   = (const float*)d_in[4];
    const float* Wv   = (const float*)d_in[5];
    const float* Wo   = (const float*)d_in[6];
    float* out = (float*)d_out;

    __nv_bfloat16 *xh, *xl, *wh, *wl, *aoh, *aol;
    cudaGetSymbolAddress((void**)&xh,  g_xh);
    cudaGetSymbolAddress((void**)&xl,  g_xl);
    cudaGetSymbolAddress((void**)&wh,  g_wh);
    cudaGetSymbolAddress((void**)&wl,  g_wl);
    cudaGetSymbolAddress((void**)&aoh, g_aoh);
    cudaGetSymbolAddress((void**)&aol, g_aol);

    cudaFuncSetAttribute(attn_mma_kernel,
                         cudaFuncAttributeMaxDynamicSharedMemorySize, SMEM_ATTN);
    cudaFuncSetAttribute(gemm_mma_kernel<0>,
                         cudaFuncAttributeMaxDynamicSharedMemorySize, SMEM_GEMM);
    cudaFuncSetAttribute(gemm_mma_kernel<3>,
                         cudaFuncAttributeMaxDynamicSharedMemorySize, SMEM_GEMM);

    static cudaStream_t s1 = nullptr, s2 = nullptr;
    static cudaEvent_t ev_root = nullptr, ev_wv = nullptr, ev_wo = nullptr,
                       ev_a0 = nullptr, ev_s2 = nullptr;
    if (!s1) {
        cudaStreamCreateWithFlags(&s1, cudaStreamNonBlocking);
        cudaStreamCreateWithFlags(&s2, cudaStreamNonBlocking);
        cudaEventCreateWithFlags(&ev_root, cudaEventDisableTiming);
        cudaEventCreateWithFlags(&ev_wv,   cudaEventDisableTiming);
        cudaEventCreateWithFlags(&ev_wo,   cudaEventDisableTiming);
        cudaEventCreateWithFlags(&ev_a0,   cudaEventDisableTiming);
        cudaEventCreateWithFlags(&ev_s2,   cudaEventDisableTiming);
    }

    const size_t WSZ = (size_t)GN * GK;
    const int n4x = GM * GK / 4;
    const int n4w = GN * GK / 4;

    // fork: weight cvts on s1 overlap x cvt on main
    cudaEventRecord(ev_root, 0);
    cudaStreamWaitEvent(s1, ev_root, 0);
    cvt_split_kernel<<<(n4w + 255) / 256, 256, 0, s1>>>(Wq, wh + 0 * WSZ, wl + 0 * WSZ, n4w);
    cvt_split_kernel<<<(n4w + 255) / 256, 256, 0, s1>>>(Wk, wh + 1 * WSZ, wl + 1 * WSZ, n4w);
    cvt_split_kernel<<<(n4w + 255) / 256, 256, 0, s1>>>(Wv, wh + 2 * WSZ, wl + 2 * WSZ, n4w);
    cudaEventRecord(ev_wv, s1);
    cvt_split_kernel<<<(n4w + 255) / 256, 256, 0, s1>>>(Wo, wh + 3 * WSZ, wl + 3 * WSZ, n4w);
    cudaEventRecord(ev_wo, s1);

    // main: x cvt, fused QKV GEMM (RoPE in epilogue), then attention b=0
    cvt_split_kernel<<<(n4x + 255) / 256, 256>>>(x, xh, xl, n4x);
    cudaStreamWaitEvent(0, ev_wv, 0);
    gemm_mma_kernel<3><<<dim3(3 * GN / 128, GM / 128), 256, SMEM_GEMM>>>(
        xh, xl, wh, wl, nullptr, cosb, sinb, 0);

    attn_mma_kernel<<<dim3(CT / 128, CNH), 256, SMEM_ATTN>>>(0);
    cudaEventRecord(ev_a0, 0);
    attn_mma_kernel<<<dim3(CT / 128, CNH), 256, SMEM_ATTN>>>(1);

    // s2: Wo for b=0 rows overlaps attention b=1
    cudaStreamWaitEvent(s2, ev_a0, 0);
    cudaStreamWaitEvent(s2, ev_wo, 0);
    gemm_mma_kernel<0><<<dim3(GN / 128, GM / 256), 256, SMEM_GEMM, s2>>>(
        aoh, aol, wh + 3 * WSZ, wl + 3 * WSZ, out, nullptr, nullptr, 0);
    cudaEventRecord(ev_s2, s2);

    // main: Wo for b=1 rows, then join s2
    cudaStreamWaitEvent(0, ev_wo, 0);
    gemm_mma_kernel<0><<<dim3(GN / 128, GM / 256), 256, SMEM_GEMM>>>(
        aoh, aol, wh + 3 * WSZ, wl + 3 * WSZ, out, nullptr, nullptr, GM / 2 * 0 + 2048);
    cudaStreamWaitEvent(0, ev_s2, 0);
}